// round 8
// baseline (speedup 1.0000x reference)
#include <cuda_runtime.h>
#include <cuda_bf16.h>
#include <cstdint>

#define BB 8
#define HWN 65536
#define NCHUNK 128
#define PART_STRIDE 1296

typedef uint32_t u32;

// ================= device scratch =================
__device__ __align__(16) __nv_bfloat16 g_in[(size_t)4 * 8 * HWN * 64];
#define PLANE(v, cg, b) (((size_t)(((v) * 2 + (cg)) * 8 + (b))) << 22)
__device__ __align__(16) float g_U[(size_t)BB * 16 * HWN];
__device__ __align__(16) __nv_bfloat16 g_Uh[(size_t)BB * HWN * 16];
__device__ __align__(16) __nv_bfloat16 g_Ul[(size_t)BB * HWN * 16];
__device__ __align__(16) float g_part[BB * NCHUNK * PART_STRIDE];
__device__ __align__(16) float g_PF2[BB * 16 * 64];
__device__ __align__(16) unsigned char g_Wc1[73728];
__device__ __align__(16) unsigned char g_Wc2[147456];
__device__ __align__(16) __nv_bfloat16 g_W2[(size_t)BB * 18432];

// ================= helpers =================
__device__ __forceinline__ u32 smem_u32(const void* p) {
    u32 a;
    asm("{ .reg .u64 t; cvta.to.shared.u64 t, %1; cvt.u32.u64 %0, t; }" : "=r"(a) : "l"(p));
    return a;
}
__device__ __forceinline__ void ldm4(u32* r, u32 a) {
    asm volatile("ldmatrix.sync.aligned.m8n8.x4.shared.b16 {%0,%1,%2,%3}, [%4];"
                 : "=r"(r[0]), "=r"(r[1]), "=r"(r[2]), "=r"(r[3]) : "r"(a));
}
__device__ __forceinline__ void mma16816(float* c, const u32* a, const u32* b) {
    asm volatile("mma.sync.aligned.m16n8k16.row.col.f32.bf16.bf16.f32 "
                 "{%0,%1,%2,%3}, {%4,%5,%6,%7}, {%8,%9}, {%0,%1,%2,%3};"
                 : "+f"(c[0]), "+f"(c[1]), "+f"(c[2]), "+f"(c[3])
                 : "r"(a[0]), "r"(a[1]), "r"(a[2]), "r"(a[3]), "r"(b[0]), "r"(b[1]));
}
__device__ __forceinline__ void split(float f, __nv_bfloat16& h, __nv_bfloat16& l) {
    h = __float2bfloat16(f);
    l = __float2bfloat16(f - __bfloat162float(h));
}
__device__ __forceinline__ void cpa16(u32 dst, const void* src, bool pred) {
    unsigned sz = pred ? 16u : 0u;
    asm volatile("cp.async.cg.shared.global [%0], [%1], 16, %2;"
                 :: "r"(dst), "l"(__cvta_generic_to_global(src)), "r"(sz));
}
#define CP_COMMIT() asm volatile("cp.async.commit_group;" ::: "memory")
#define CP_WAIT0()  asm volatile("cp.async.wait_group 0;" ::: "memory")

// ================= weight prep =================
__global__ void prep_w_kernel(const float* __restrict__ Ws, const float* __restrict__ Wc) {
    int id = blockIdx.x * 256 + threadIdx.x;
    if (id < 64 * 1152) {
        int oc = id / 1152, rem = id - oc * 1152, ic = rem / 9, tap = rem - ic * 9;
        if (ic < 64) {
            __nv_bfloat16 h, l;
            split(Wc[id], h, l);
            u32 off = (u32)((tap * 64 + oc) * 128) + (u32)((ic * 2) ^ ((oc & 7) << 4));
            *(__nv_bfloat16*)(g_Wc2 + off) = h;
            *(__nv_bfloat16*)(g_Wc2 + off + 73728) = l;
        }
    }
    if (id < 16 * 1152) {
        int oc = id / 1152, rem = id - oc * 1152, ic = rem / 9, tap = rem - ic * 9;
        __nv_bfloat16 h, l;
        split(Ws[id], h, l);
        u32 off = (u32)((tap * 16 + oc) * 256) + (u32)((ic * 2) ^ ((oc & 7) << 4));
        *(__nv_bfloat16*)(g_Wc1 + off) = h;
        *(__nv_bfloat16*)(g_Wc1 + off + 36864) = l;
    }
}

// ================= NCHW fp32 -> NHWC bf16 hi/lo =================
__global__ __launch_bounds__(256)
void convert_kernel(const float* __restrict__ x, const float* __restrict__ bridge) {
    __shared__ float sT[64][68];
    int b = blockIdx.z, cg = blockIdx.y, pb = blockIdx.x;
    const float* src = cg ? bridge : x;
    int tid = threadIdx.x;
    int p0 = pb * 64;
    for (int i = tid; i < 64 * 64; i += 256) {
        int c = i >> 6, px = i & 63;
        sT[c][px] = src[((size_t)(b * 64 + c) << 16) + p0 + px];
    }
    __syncthreads();
    for (int i = tid; i < 512; i += 256) {
        int px = i >> 3, c8 = i & 7;
        __nv_bfloat16 hb[8], lb[8];
#pragma unroll
        for (int j = 0; j < 8; j++)
            split(sT[c8 * 8 + j][px], hb[j], lb[j]);
        size_t base = ((size_t)(p0 + px) << 6) + c8 * 8;
        *(uint4*)&g_in[PLANE(0, cg, b) + base] = *(uint4*)hb;
        *(uint4*)&g_in[PLANE(1, cg, b) + base] = *(uint4*)lb;
    }
}

// ================= conv1: strip 64px x 32y, 512 threads, 2 rows/iter =================
#define C1_SLOT0 73728
#define C1_SLOTSZ 33792

__device__ __forceinline__ void c1_stage(u32 sb, int b, int x0, int ys, u32 slot, int tid) {
    bool yok = (unsigned)ys < 256u;
    int ysc = yok ? ys : 0;
    for (int i = tid; i < 2112; i += 512) {
        int p = i / 528, j = i - p * 528;
        int px = j >> 3, c8 = j & 7;
        int gx = x0 - 1 + px;
        bool ok = yok && (unsigned)gx < 256u;
        int gxc = ((unsigned)gx < 256u) ? gx : 0;
        const void* src = &g_in[PLANE(p & 1, p >> 1, b) +
                                (((size_t)(ysc * 256 + gxc)) << 6) + c8 * 8];
        u32 dst = sb + slot + (u32)(p * 8448 + px * 128) +
                  (u32)((c8 * 16) ^ ((px & 7) << 4));
        cpa16(dst, src, ok);
    }
}

__global__ __launch_bounds__(512, 1)
void conv1_kernel() {
    extern __shared__ __align__(16) unsigned char sm[];
    u32 sb = smem_u32(sm);
    int tid = threadIdx.x, lane = tid & 31, wid = tid >> 5;
    int b = blockIdx.z, y0 = blockIdx.y * 32, x0 = blockIdx.x * 64;

    for (int i = tid; i < 73728 / 16; i += 512)
        ((uint4*)sm)[i] = ((const uint4*)g_Wc1)[i];

    int i8 = lane & 7, a_mh = (lane >> 3) & 1, a_kh = lane >> 4;
    int bq = lane >> 3;
    int wm = wid & 3, wn = (wid >> 2) & 1, ym = wid >> 3;
    int apx = wm * 16 + a_mh * 8 + i8;
    int ocw2 = wn * 8 + i8;
    u32 bRow = (u32)(ocw2 * 256), kxor = (u32)((ocw2 & 7) << 4);
    int g = lane >> 2, t4 = lane & 3;

    // prologue: rows y0-1 .. y0+2 into slots 3,0,1,2
    c1_stage(sb, b, x0, y0 - 1, C1_SLOT0 + 3u * C1_SLOTSZ, tid);
    c1_stage(sb, b, x0, y0 + 0, C1_SLOT0 + 0u * C1_SLOTSZ, tid);
    c1_stage(sb, b, x0, y0 + 1, C1_SLOT0 + 1u * C1_SLOTSZ, tid);
    c1_stage(sb, b, x0, y0 + 2, C1_SLOT0 + 2u * C1_SLOTSZ, tid);
    CP_COMMIT();
    CP_WAIT0();
    __syncthreads();

    for (int t = 0; t < 16; t++) {
        int y = 2 * t + ym;                  // row this warp computes

        float acc[4] = {0.f, 0.f, 0.f, 0.f};
#pragma unroll
        for (int ky = 0; ky < 3; ky++) {
            u32 sl = sb + C1_SLOT0 + (u32)(((y + ky - 1) & 3)) * C1_SLOTSZ;
#pragma unroll
            for (int kx = 0; kx < 3; kx++) {
                int tap = ky * 3 + kx;
                int p = apx + kx;
                u32 aoff = (u32)(p * 128);
                u32 asw = (u32)((p & 7) << 4);
#pragma unroll
                for (int cg = 0; cg < 2; cg++) {
                    u32 pb2 = sl + (u32)(cg * 16896);
#pragma unroll
                    for (int pr = 0; pr < 2; pr++) {
                        u32 bA = sb + (u32)(tap * 4096) + bRow +
                                 ((u32)(cg * 128 + pr * 64 + bq * 16) ^ kxor);
                        u32 BH[4], BL[4];
                        ldm4(BH, bA);
                        ldm4(BL, bA + 36864);
#pragma unroll
                        for (int kcin = 0; kcin < 2; kcin++) {
                            int kc = pr * 2 + kcin;
                            u32 aH = pb2 + aoff + ((u32)(kc * 32 + a_kh * 16) ^ asw);
                            u32 Ah[4], Al[4];
                            ldm4(Ah, aH);
                            ldm4(Al, aH + 8448);
                            mma16816(acc, Ah, BH + 2 * kcin);
                            mma16816(acc, Al, BH + 2 * kcin);
                            mma16816(acc, Ah, BL + 2 * kcin);
                        }
                    }
                }
            }
        }
        // writeout: fp32 U + bf16 hi/lo
        int yy = y0 + y;
        int px = x0 + wm * 16 + g;
        int oc = wn * 8 + 2 * t4;
        size_t rowb = (size_t)yy * 256 + px;
        g_U[((size_t)(b * 16 + oc) << 16) + rowb] = acc[0];
        g_U[((size_t)(b * 16 + oc + 1) << 16) + rowb] = acc[1];
        g_U[((size_t)(b * 16 + oc) << 16) + rowb + 8] = acc[2];
        g_U[((size_t)(b * 16 + oc + 1) << 16) + rowb + 8] = acc[3];
        __nv_bfloat16 h0, l0, h1, l1;
        split(acc[0], h0, l0);
        split(acc[1], h1, l1);
        size_t idx = ((size_t)b * HWN + rowb) * 16 + oc;
        __nv_bfloat162 hh, ll;
        hh.x = h0; hh.y = h1; ll.x = l0; ll.y = l1;
        *(__nv_bfloat162*)&g_Uh[idx] = hh;
        *(__nv_bfloat162*)&g_Ul[idx] = ll;
        split(acc[2], h0, l0);
        split(acc[3], h1, l1);
        hh.x = h0; hh.y = h1; ll.x = l0; ll.y = l1;
        *(__nv_bfloat162*)&g_Uh[idx + 128] = hh;
        *(__nv_bfloat162*)&g_Ul[idx + 128] = ll;

        __syncthreads();                     // all warps done reading this pair's slots
        if (t < 15) {
            c1_stage(sb, b, x0, y0 + 2 * t + 3,
                     C1_SLOT0 + (u32)((2 * t + 3) & 3) * C1_SLOTSZ, tid);
            c1_stage(sb, b, x0, y0 + 2 * t + 4,
                     C1_SLOT0 + (u32)((2 * t + 4) & 3) * C1_SLOTSZ, tid);
            CP_COMMIT();
            CP_WAIT0();
            __syncthreads();
        }
    }
}

// ================= reduction (fp32, unchanged) =================
__global__ __launch_bounds__(256)
void reduce_kernel(const float* __restrict__ bridge) {
    __shared__ __align__(16) float sU[16][68];
    __shared__ __align__(16) float sB[64][68];
    int b = blockIdx.y, ch = blockIdx.x;
    int tid = threadIdx.x;
    int s = tid >> 4, q = tid & 15;
    int n0 = ch * 512;
    const float* Ub = g_U + (size_t)b * 16 * HWN;
    const float* Bb = bridge + (size_t)b * 64 * HWN;
    float accG[4] = {0.f, 0.f, 0.f, 0.f};
    float accM = 0.f, accR = 0.f;
    for (int sub = 0; sub < 8; sub++) {
        int n = n0 + sub * 64;
        {
            int sl = tid >> 4, p4 = (tid & 15) * 4;
            *reinterpret_cast<float4*>(&sU[sl][p4]) =
                *reinterpret_cast<const float4*>(&Ub[sl * HWN + n + p4]);
        }
#pragma unroll
        for (int r = 0; r < 4; r++) {
            int cl = (tid >> 4) + r * 16;
            int p4 = (tid & 15) * 4;
            *reinterpret_cast<float4*>(&sB[cl][p4]) =
                *reinterpret_cast<const float4*>(&Bb[cl * HWN + n + p4]);
        }
        __syncthreads();
#pragma unroll
        for (int p = 0; p < 64; p += 4) {
            float4 u = *reinterpret_cast<float4*>(&sU[s][p]);
            float4 t4 = *reinterpret_cast<float4*>(&sU[q][p]);
            accM += u.x * t4.x + u.y * t4.y + u.z * t4.z + u.w * t4.w;
#pragma unroll
            for (int j = 0; j < 4; j++) {
                float4 bv = *reinterpret_cast<float4*>(&sB[q + j * 16][p]);
                accG[j] += u.x * bv.x + u.y * bv.y + u.z * bv.z + u.w * bv.w;
            }
            if (q == 0) accR += fabsf(u.x) + fabsf(u.y) + fabsf(u.z) + fabsf(u.w);
        }
        __syncthreads();
    }
    float* o = g_part + (size_t)(b * NCHUNK + ch) * PART_STRIDE;
    o[s * 16 + q] = accM;
#pragma unroll
    for (int j = 0; j < 4; j++) o[256 + s * 64 + q + j * 16] = accG[j];
    if (q == 0) o[1280 + s] = accR;
}

// ================= solve (unchanged) =================
__global__ __launch_bounds__(256)
void solve_kernel() {
    __shared__ float sGram[256];
    __shared__ float sG[1024];
    __shared__ float srr[16];
    __shared__ double A[16][17];
    __shared__ double M[16][17];
    __shared__ double spiv;
    int b = blockIdx.x;
    int tid = threadIdx.x;
    const float* base = g_part + (size_t)b * NCHUNK * PART_STRIDE;
    {
        float a = 0.f;
        for (int ch = 0; ch < NCHUNK; ch++) a += base[ch * PART_STRIDE + tid];
        sGram[tid] = a;
    }
#pragma unroll
    for (int j = 0; j < 4; j++) {
        int e = tid + j * 256;
        float a = 0.f;
        for (int ch = 0; ch < NCHUNK; ch++) a += base[ch * PART_STRIDE + 256 + e];
        sG[e] = a;
    }
    if (tid < 16) {
        float a = 0.f;
        for (int ch = 0; ch < NCHUNK; ch++) a += base[ch * PART_STRIDE + 1280 + tid];
        srr[tid] = 1e-6f + a;
    }
    __syncthreads();
    {
        int i = tid >> 4, t = tid & 15;
        A[i][t] = (double)sGram[tid] / ((double)srr[i] * (double)srr[t]);
        M[i][t] = (i == t) ? 1.0 : 0.0;
    }
    __syncthreads();
    for (int k = 0; k < 16; k++) {
        if (tid == 0) spiv = 1.0 / A[k][k];
        __syncthreads();
        if (tid < 16) { A[k][tid] *= spiv; M[k][tid] *= spiv; }
        __syncthreads();
        int i = tid >> 4, t = tid & 15;
        double f = A[i][k];
        __syncthreads();
        if (i != k) { A[i][t] -= f * A[k][t]; M[i][t] -= f * M[k][t]; }
        __syncthreads();
    }
#pragma unroll
    for (int j = 0; j < 4; j++) {
        int e = tid + j * 256;
        int s = e >> 6, c = e & 63;
        double v = 0.0;
#pragma unroll
        for (int t = 0; t < 16; t++)
            v += M[s][t] * ((double)sG[t * 64 + c] / (double)srr[t]);
        g_PF2[b * 1024 + e] = (float)(v / (double)srr[s]);
    }
}

// ================= fold PF2 into conv2 proj-weights =================
__global__ __launch_bounds__(256)
void w2eff_kernel(const float* __restrict__ Wc) {
    __shared__ float sPF[1024];
    int b = blockIdx.x, tid = threadIdx.x;
    for (int i = tid; i < 1024; i += 256) sPF[i] = g_PF2[b * 1024 + i];
    __syncthreads();
    for (int e = tid; e < 9216; e += 256) {
        int tap = e / 1024, r = e & 1023, o = r >> 4, s = r & 15;
        float v = 0.f;
#pragma unroll
        for (int c = 0; c < 64; c++)
            v += Wc[o * 1152 + (64 + c) * 9 + tap] * sPF[s * 64 + c];
        __nv_bfloat16 h, l;
        split(v, h, l);
        g_W2[(size_t)b * 18432 + (size_t)(tap * 1024 + o * 16 + s)] = h;
        g_W2[(size_t)b * 18432 + (size_t)(9216 + tap * 1024 + o * 16 + s)] = l;
    }
}

// ================= conv2: strip 32px x 32y, 512 threads, 2 rows/iter =================
#define C2_SLOT0 184320
#define C2_SLOTSZ 10880

__device__ __forceinline__ void c2_stage(u32 sb, int b, int x0, int ys, u32 slot, int tid) {
    bool yok = (unsigned)ys < 256u;
    int ysc = yok ? ys : 0;
    for (int i = tid; i < 680; i += 512) {
        if (i < 544) {
            int var = i >= 272;
            int j = i - var * 272;
            int px = j >> 3, c8 = j & 7;
            int gx = x0 - 1 + px;
            bool ok = yok && (unsigned)gx < 256u;
            int gxc = ((unsigned)gx < 256u) ? gx : 0;
            const void* src = &g_in[PLANE(var, 0, b) +
                                    (((size_t)(ysc * 256 + gxc)) << 6) + c8 * 8];
            u32 dst = sb + slot + (u32)(var * 4352 + px * 128) +
                      (u32)((c8 * 16) ^ ((px & 7) << 4));
            cpa16(dst, src, ok);
        } else {
            int j = i - 544;
            int var = j >= 68;
            int jj = j - var * 68;
            int px = jj >> 1, hf = jj & 1;
            int gx = x0 - 1 + px;
            bool ok = yok && (unsigned)gx < 256u;
            int gxc = ((unsigned)gx < 256u) ? gx : 0;
            const __nv_bfloat16* bp = var ? g_Ul : g_Uh;
            const void* src = &bp[((size_t)b * HWN + (size_t)(ysc * 256 + gxc)) * 16 + hf * 8];
            u32 dst = sb + slot + 8704 + (u32)(var * 1088 + px * 32 + hf * 16);
            cpa16(dst, src, ok);
        }
    }
}

__global__ __launch_bounds__(512, 1)
void conv2_kernel(const float* __restrict__ x, float* __restrict__ out) {
    extern __shared__ __align__(16) unsigned char sm[];
    u32 sb = smem_u32(sm);
    int tid = threadIdx.x, lane = tid & 31, wid = tid >> 5;
    int b = blockIdx.z, y0 = blockIdx.y * 32, x0 = blockIdx.x * 32;

    for (int i = tid; i < 147456 / 16; i += 512)
        ((uint4*)sm)[i] = ((const uint4*)g_Wc2)[i];
    for (int i = tid; i < 36864 / 16; i += 512)
        ((uint4*)(sm + 147456))[i] = ((const uint4*)(g_W2 + (size_t)b * 18432))[i];

    int i8 = lane & 7, a_mh = (lane >> 3) & 1, a_kh = lane >> 4;
    int b_kh = (lane >> 3) & 1, b_nh = lane >> 4;
    int wm = wid & 1, wn = (wid >> 1) & 3, ym = wid >> 3;
    int apx = wm * 16 + a_mh * 8 + i8;
    int ocw = wn * 16 + b_nh * 8 + i8;
    u32 bRow = (u32)(ocw * 128), bSw = (u32)((ocw & 7) << 4);
    u32 bRowU = (u32)(ocw * 32);
    int g = lane >> 2, t4 = lane & 3;

    // prologue: rows y0-1 .. y0+2 into slots 3,0,1,2
    c2_stage(sb, b, x0, y0 - 1, C2_SLOT0 + 3u * C2_SLOTSZ, tid);
    c2_stage(sb, b, x0, y0 + 0, C2_SLOT0 + 0u * C2_SLOTSZ, tid);
    c2_stage(sb, b, x0, y0 + 1, C2_SLOT0 + 1u * C2_SLOTSZ, tid);
    c2_stage(sb, b, x0, y0 + 2, C2_SLOT0 + 2u * C2_SLOTSZ, tid);
    CP_COMMIT();
    CP_WAIT0();
    __syncthreads();

    for (int t = 0; t < 16; t++) {
        int y = 2 * t + ym;

        float acc[2][4];
#pragma unroll
        for (int j = 0; j < 2; j++)
#pragma unroll
            for (int q = 0; q < 4; q++) acc[j][q] = 0.f;

#pragma unroll
        for (int ky = 0; ky < 3; ky++) {
            u32 sl = sb + C2_SLOT0 + (u32)(((y + ky - 1) & 3)) * C2_SLOTSZ;
#pragma unroll
            for (int kx = 0; kx < 3; kx++) {
                int tap = ky * 3 + kx;
                int p = apx + kx;
                u32 aoff = (u32)(p * 128);
                u32 asw = (u32)((p & 7) << 4);
#pragma unroll
                for (int kc = 0; kc < 4; kc++) {
                    u32 aH = sl + aoff + ((u32)(kc * 32 + a_kh * 16) ^ asw);
                    u32 Ah[4], Al[4], BH[4], BL[4];
                    ldm4(Ah, aH);
                    ldm4(Al, aH + 4352);
                    u32 bA = sb + (u32)(tap * 8192) + bRow +
                             ((u32)(kc * 32 + b_kh * 16) ^ bSw);
                    ldm4(BH, bA);
                    ldm4(BL, bA + 73728);
#pragma unroll
                    for (int j = 0; j < 2; j++) {
                        mma16816(acc[j], Ah, BH + 2 * j);
                        mma16816(acc[j], Al, BH + 2 * j);
                        mma16816(acc[j], Ah, BL + 2 * j);
                    }
                }
                // U part (k16 over 16 subspace channels)
                {
                    u32 aU = sl + 8704 + (u32)(p * 32 + a_kh * 16);
                    u32 AUh[4], AUl[4], BUh[4], BUl[4];
                    ldm4(AUh, aU);
                    ldm4(AUl, aU + 1088);
                    u32 bU = sb + 147456 + (u32)(tap * 2048) + bRowU + (u32)(b_kh * 16);
                    ldm4(BUh, bU);
                    ldm4(BUl, bU + 18432);
#pragma unroll
                    for (int j = 0; j < 2; j++) {
                        mma16816(acc[j], AUh, BUh + 2 * j);
                        mma16816(acc[j], AUl, BUh + 2 * j);
                        mma16816(acc[j], AUh, BUl + 2 * j);
                    }
                }
            }
        }
        // writeout + residual
        int yy = y0 + y;
        int px = x0 + wm * 16 + g;
        size_t rowb = (size_t)yy * 256 + px;
#pragma unroll
        for (int j = 0; j < 2; j++) {
            int oc = wn * 16 + j * 8 + 2 * t4;
            size_t o0 = ((size_t)(b * 64 + oc) << 16) + rowb;
            size_t o1 = o0 + HWN;
            out[o0] = acc[j][0] + x[o0];
            out[o1] = acc[j][1] + x[o1];
            out[o0 + 8] = acc[j][2] + x[o0 + 8];
            out[o1 + 8] = acc[j][3] + x[o1 + 8];
        }

        __syncthreads();
        if (t < 15) {
            c2_stage(sb, b, x0, y0 + 2 * t + 3,
                     C2_SLOT0 + (u32)((2 * t + 3) & 3) * C2_SLOTSZ, tid);
            c2_stage(sb, b, x0, y0 + 2 * t + 4,
                     C2_SLOT0 + (u32)((2 * t + 4) & 3) * C2_SLOTSZ, tid);
            CP_COMMIT();
            CP_WAIT0();
            __syncthreads();
        }
    }
}

// ================= launch =================
extern "C" void kernel_launch(void* const* d_in, const int* in_sizes, int n_in,
                              void* d_out, int out_size) {
    const float* x      = (const float*)d_in[0];
    const float* bridge = (const float*)d_in[1];
    const float* Wsub   = (const float*)d_in[2];
    const float* Wcb    = (const float*)d_in[3];
    float* out = (float*)d_out;

    cudaFuncSetAttribute(conv1_kernel, cudaFuncAttributeMaxDynamicSharedMemorySize, 208896);
    cudaFuncSetAttribute(conv2_kernel, cudaFuncAttributeMaxDynamicSharedMemorySize, 227840);

    prep_w_kernel<<<288, 256>>>(Wsub, Wcb);
    convert_kernel<<<dim3(1024, 2, 8), 256>>>(x, bridge);
    conv1_kernel<<<dim3(4, 8, 8), 512, 208896>>>();
    reduce_kernel<<<dim3(NCHUNK, BB), 256>>>(bridge);
    solve_kernel<<<BB, 256>>>();
    w2eff_kernel<<<BB, 256>>>(Wcb);
    conv2_kernel<<<dim3(8, 8, 8), 512, 227840>>>(x, out);
}

// round 10
// speedup vs baseline: 1.1669x; 1.1669x over previous
#include <cuda_runtime.h>
#include <cuda_bf16.h>
#include <cstdint>

#define BB 8
#define HWN 65536
#define NCHUNK 128
#define PART_STRIDE 1296

typedef uint32_t u32;

// ================= device scratch =================
__device__ __align__(16) __nv_bfloat16 g_in[(size_t)4 * 8 * HWN * 64];
#define PLANE(v, cg, b) (((size_t)(((v) * 2 + (cg)) * 8 + (b))) << 22)
__device__ __align__(16) float g_U[(size_t)BB * 16 * HWN];
__device__ __align__(16) __nv_bfloat16 g_Uh[(size_t)BB * HWN * 16];
__device__ __align__(16) __nv_bfloat16 g_Ul[(size_t)BB * HWN * 16];
__device__ __align__(16) float g_part[BB * NCHUNK * PART_STRIDE];
__device__ __align__(16) float g_PF2[BB * 16 * 64];
__device__ __align__(16) unsigned char g_Wc1[73728];
// conv2 x-weights, ochalf-major: [oh][var][tap][32oc][64ic] (147456 B)
__device__ __align__(16) unsigned char g_Wc2[147456];
// conv2 U-weights per batch: [b][oh][var][tap][32oc][16s] (bf16 elements)
__device__ __align__(16) __nv_bfloat16 g_W2[(size_t)BB * 18432];

// ================= helpers =================
__device__ __forceinline__ u32 smem_u32(const void* p) {
    u32 a;
    asm("{ .reg .u64 t; cvta.to.shared.u64 t, %1; cvt.u32.u64 %0, t; }" : "=r"(a) : "l"(p));
    return a;
}
__device__ __forceinline__ void ldm4(u32* r, u32 a) {
    asm volatile("ldmatrix.sync.aligned.m8n8.x4.shared.b16 {%0,%1,%2,%3}, [%4];"
                 : "=r"(r[0]), "=r"(r[1]), "=r"(r[2]), "=r"(r[3]) : "r"(a));
}
__device__ __forceinline__ void mma16816(float* c, const u32* a, const u32* b) {
    asm volatile("mma.sync.aligned.m16n8k16.row.col.f32.bf16.bf16.f32 "
                 "{%0,%1,%2,%3}, {%4,%5,%6,%7}, {%8,%9}, {%0,%1,%2,%3};"
                 : "+f"(c[0]), "+f"(c[1]), "+f"(c[2]), "+f"(c[3])
                 : "r"(a[0]), "r"(a[1]), "r"(a[2]), "r"(a[3]), "r"(b[0]), "r"(b[1]));
}
__device__ __forceinline__ void split(float f, __nv_bfloat16& h, __nv_bfloat16& l) {
    h = __float2bfloat16(f);
    l = __float2bfloat16(f - __bfloat162float(h));
}
__device__ __forceinline__ void cpa16(u32 dst, const void* src, bool pred) {
    unsigned sz = pred ? 16u : 0u;
    asm volatile("cp.async.cg.shared.global [%0], [%1], 16, %2;"
                 :: "r"(dst), "l"(__cvta_generic_to_global(src)), "r"(sz));
}
#define CP_COMMIT() asm volatile("cp.async.commit_group;" ::: "memory")
#define CP_WAIT0()  asm volatile("cp.async.wait_group 0;" ::: "memory")

// ================= weight prep =================
__global__ void prep_w_kernel(const float* __restrict__ Ws, const float* __restrict__ Wc) {
    int id = blockIdx.x * 256 + threadIdx.x;
    if (id < 64 * 1152) {
        int oc = id / 1152, rem = id - oc * 1152, ic = rem / 9, tap = rem - ic * 9;
        if (ic < 64) {
            __nv_bfloat16 h, l;
            split(Wc[id], h, l);
            int oh = oc >> 5, ocl = oc & 31;
            u32 off = (u32)(oh * 73728 + tap * 4096 + ocl * 128) +
                      (u32)((ic * 2) ^ ((ocl & 7) << 4));
            *(__nv_bfloat16*)(g_Wc2 + off) = h;
            *(__nv_bfloat16*)(g_Wc2 + off + 36864) = l;
        }
    }
    if (id < 16 * 1152) {
        int oc = id / 1152, rem = id - oc * 1152, ic = rem / 9, tap = rem - ic * 9;
        __nv_bfloat16 h, l;
        split(Ws[id], h, l);
        u32 off = (u32)((tap * 16 + oc) * 256) + (u32)((ic * 2) ^ ((oc & 7) << 4));
        *(__nv_bfloat16*)(g_Wc1 + off) = h;
        *(__nv_bfloat16*)(g_Wc1 + off + 36864) = l;
    }
}

// ================= NCHW fp32 -> NHWC bf16 hi/lo =================
__global__ __launch_bounds__(256)
void convert_kernel(const float* __restrict__ x, const float* __restrict__ bridge) {
    __shared__ float sT[64][68];
    int b = blockIdx.z, cg = blockIdx.y, pb = blockIdx.x;
    const float* src = cg ? bridge : x;
    int tid = threadIdx.x;
    int p0 = pb * 64;
    for (int i = tid; i < 64 * 64; i += 256) {
        int c = i >> 6, px = i & 63;
        sT[c][px] = src[((size_t)(b * 64 + c) << 16) + p0 + px];
    }
    __syncthreads();
    for (int i = tid; i < 512; i += 256) {
        int px = i >> 3, c8 = i & 7;
        __nv_bfloat16 hb[8], lb[8];
#pragma unroll
        for (int j = 0; j < 8; j++)
            split(sT[c8 * 8 + j][px], hb[j], lb[j]);
        size_t base = ((size_t)(p0 + px) << 6) + c8 * 8;
        *(uint4*)&g_in[PLANE(0, cg, b) + base] = *(uint4*)hb;
        *(uint4*)&g_in[PLANE(1, cg, b) + base] = *(uint4*)lb;
    }
}

// ================= conv1: strip 64px x 32y, 4-slot row rotation (R6 version) =================
#define C1_SLOT0 73728
#define C1_SLOTSZ 33792

__device__ __forceinline__ void c1_stage(u32 sb, int b, int x0, int ys, u32 slot, int tid) {
    bool yok = (unsigned)ys < 256u;
    int ysc = yok ? ys : 0;
    for (int i = tid; i < 2112; i += 256) {
        int p = i / 528, j = i - p * 528;
        int px = j >> 3, c8 = j & 7;
        int gx = x0 - 1 + px;
        bool ok = yok && (unsigned)gx < 256u;
        int gxc = ((unsigned)gx < 256u) ? gx : 0;
        const void* src = &g_in[PLANE(p & 1, p >> 1, b) +
                                (((size_t)(ysc * 256 + gxc)) << 6) + c8 * 8];
        u32 dst = sb + slot + (u32)(p * 8448 + px * 128) +
                  (u32)((c8 * 16) ^ ((px & 7) << 4));
        cpa16(dst, src, ok);
    }
}

__global__ __launch_bounds__(256, 1)
void conv1_kernel() {
    extern __shared__ __align__(16) unsigned char sm[];
    u32 sb = smem_u32(sm);
    int tid = threadIdx.x, lane = tid & 31, wid = tid >> 5;
    int b = blockIdx.z, y0 = blockIdx.y * 32, x0 = blockIdx.x * 64;

    for (int i = tid; i < 73728 / 16; i += 256)
        ((uint4*)sm)[i] = ((const uint4*)g_Wc1)[i];

    int i8 = lane & 7, a_mh = (lane >> 3) & 1, a_kh = lane >> 4;
    int bq = lane >> 3;
    int wm = wid & 3, wn = wid >> 2;
    int apx = wm * 16 + a_mh * 8 + i8;
    int ocw2 = wn * 8 + i8;
    u32 bRow = (u32)(ocw2 * 256), kxor = (u32)((ocw2 & 7) << 4);
    int g = lane >> 2, t4 = lane & 3;

    c1_stage(sb, b, x0, y0 - 1, C1_SLOT0 + 3u * C1_SLOTSZ, tid);
    c1_stage(sb, b, x0, y0 + 0, C1_SLOT0 + 0u * C1_SLOTSZ, tid);
    c1_stage(sb, b, x0, y0 + 1, C1_SLOT0 + 1u * C1_SLOTSZ, tid);
    CP_COMMIT();

    for (int y = 0; y < 32; y++) {
        CP_WAIT0();
        __syncthreads();
        if (y + 2 <= 32)
            c1_stage(sb, b, x0, y0 + y + 2, C1_SLOT0 + (u32)((y + 2) & 3) * C1_SLOTSZ, tid);
        CP_COMMIT();

        float acc[4] = {0.f, 0.f, 0.f, 0.f};
#pragma unroll
        for (int ky = 0; ky < 3; ky++) {
            u32 sl = sb + C1_SLOT0 + (u32)(((y + ky - 1) & 3)) * C1_SLOTSZ;
#pragma unroll
            for (int kx = 0; kx < 3; kx++) {
                int tap = ky * 3 + kx;
                int p = apx + kx;
                u32 aoff = (u32)(p * 128);
                u32 asw = (u32)((p & 7) << 4);
#pragma unroll
                for (int cg = 0; cg < 2; cg++) {
                    u32 pb2 = sl + (u32)(cg * 16896);
#pragma unroll
                    for (int pr = 0; pr < 2; pr++) {
                        u32 bA = sb + (u32)(tap * 4096) + bRow +
                                 ((u32)(cg * 128 + pr * 64 + bq * 16) ^ kxor);
                        u32 BH[4], BL[4];
                        ldm4(BH, bA);
                        ldm4(BL, bA + 36864);
#pragma unroll
                        for (int kcin = 0; kcin < 2; kcin++) {
                            int kc = pr * 2 + kcin;
                            u32 aH = pb2 + aoff + ((u32)(kc * 32 + a_kh * 16) ^ asw);
                            u32 Ah[4], Al[4];
                            ldm4(Ah, aH);
                            ldm4(Al, aH + 8448);
                            mma16816(acc, Ah, BH + 2 * kcin);
                            mma16816(acc, Al, BH + 2 * kcin);
                            mma16816(acc, Ah, BL + 2 * kcin);
                        }
                    }
                }
            }
        }
        // writeout: fp32 U + bf16 hi/lo
        int yy = y0 + y;
        int px = x0 + wm * 16 + g;
        int oc = wn * 8 + 2 * t4;
        size_t rowb = (size_t)yy * 256 + px;
        g_U[((size_t)(b * 16 + oc) << 16) + rowb] = acc[0];
        g_U[((size_t)(b * 16 + oc + 1) << 16) + rowb] = acc[1];
        g_U[((size_t)(b * 16 + oc) << 16) + rowb + 8] = acc[2];
        g_U[((size_t)(b * 16 + oc + 1) << 16) + rowb + 8] = acc[3];
        __nv_bfloat16 h0, l0, h1, l1;
        split(acc[0], h0, l0);
        split(acc[1], h1, l1);
        size_t idx = ((size_t)b * HWN + rowb) * 16 + oc;
        __nv_bfloat162 hh, ll;
        hh.x = h0; hh.y = h1; ll.x = l0; ll.y = l1;
        *(__nv_bfloat162*)&g_Uh[idx] = hh;
        *(__nv_bfloat162*)&g_Ul[idx] = ll;
        split(acc[2], h0, l0);
        split(acc[3], h1, l1);
        hh.x = h0; hh.y = h1; ll.x = l0; ll.y = l1;
        *(__nv_bfloat162*)&g_Uh[idx + 128] = hh;
        *(__nv_bfloat162*)&g_Ul[idx + 128] = ll;
    }
}

// ================= reduction (fp32, unchanged) =================
__global__ __launch_bounds__(256)
void reduce_kernel(const float* __restrict__ bridge) {
    __shared__ __align__(16) float sU[16][68];
    __shared__ __align__(16) float sB[64][68];
    int b = blockIdx.y, ch = blockIdx.x;
    int tid = threadIdx.x;
    int s = tid >> 4, q = tid & 15;
    int n0 = ch * 512;
    const float* Ub = g_U + (size_t)b * 16 * HWN;
    const float* Bb = bridge + (size_t)b * 64 * HWN;
    float accG[4] = {0.f, 0.f, 0.f, 0.f};
    float accM = 0.f, accR = 0.f;
    for (int sub = 0; sub < 8; sub++) {
        int n = n0 + sub * 64;
        {
            int sl = tid >> 4, p4 = (tid & 15) * 4;
            *reinterpret_cast<float4*>(&sU[sl][p4]) =
                *reinterpret_cast<const float4*>(&Ub[sl * HWN + n + p4]);
        }
#pragma unroll
        for (int r = 0; r < 4; r++) {
            int cl = (tid >> 4) + r * 16;
            int p4 = (tid & 15) * 4;
            *reinterpret_cast<float4*>(&sB[cl][p4]) =
                *reinterpret_cast<const float4*>(&Bb[cl * HWN + n + p4]);
        }
        __syncthreads();
#pragma unroll
        for (int p = 0; p < 64; p += 4) {
            float4 u = *reinterpret_cast<float4*>(&sU[s][p]);
            float4 t4 = *reinterpret_cast<float4*>(&sU[q][p]);
            accM += u.x * t4.x + u.y * t4.y + u.z * t4.z + u.w * t4.w;
#pragma unroll
            for (int j = 0; j < 4; j++) {
                float4 bv = *reinterpret_cast<float4*>(&sB[q + j * 16][p]);
                accG[j] += u.x * bv.x + u.y * bv.y + u.z * bv.z + u.w * bv.w;
            }
            if (q == 0) accR += fabsf(u.x) + fabsf(u.y) + fabsf(u.z) + fabsf(u.w);
        }
        __syncthreads();
    }
    float* o = g_part + (size_t)(b * NCHUNK + ch) * PART_STRIDE;
    o[s * 16 + q] = accM;
#pragma unroll
    for (int j = 0; j < 4; j++) o[256 + s * 64 + q + j * 16] = accG[j];
    if (q == 0) o[1280 + s] = accR;
}

// ================= solve (unchanged) =================
__global__ __launch_bounds__(256)
void solve_kernel() {
    __shared__ float sGram[256];
    __shared__ float sG[1024];
    __shared__ float srr[16];
    __shared__ double A[16][17];
    __shared__ double M[16][17];
    __shared__ double spiv;
    int b = blockIdx.x;
    int tid = threadIdx.x;
    const float* base = g_part + (size_t)b * NCHUNK * PART_STRIDE;
    {
        float a = 0.f;
        for (int ch = 0; ch < NCHUNK; ch++) a += base[ch * PART_STRIDE + tid];
        sGram[tid] = a;
    }
#pragma unroll
    for (int j = 0; j < 4; j++) {
        int e = tid + j * 256;
        float a = 0.f;
        for (int ch = 0; ch < NCHUNK; ch++) a += base[ch * PART_STRIDE + 256 + e];
        sG[e] = a;
    }
    if (tid < 16) {
        float a = 0.f;
        for (int ch = 0; ch < NCHUNK; ch++) a += base[ch * PART_STRIDE + 1280 + tid];
        srr[tid] = 1e-6f + a;
    }
    __syncthreads();
    {
        int i = tid >> 4, t = tid & 15;
        A[i][t] = (double)sGram[tid] / ((double)srr[i] * (double)srr[t]);
        M[i][t] = (i == t) ? 1.0 : 0.0;
    }
    __syncthreads();
    for (int k = 0; k < 16; k++) {
        if (tid == 0) spiv = 1.0 / A[k][k];
        __syncthreads();
        if (tid < 16) { A[k][tid] *= spiv; M[k][tid] *= spiv; }
        __syncthreads();
        int i = tid >> 4, t = tid & 15;
        double f = A[i][k];
        __syncthreads();
        if (i != k) { A[i][t] -= f * A[k][t]; M[i][t] -= f * M[k][t]; }
        __syncthreads();
    }
#pragma unroll
    for (int j = 0; j < 4; j++) {
        int e = tid + j * 256;
        int s = e >> 6, c = e & 63;
        double v = 0.0;
#pragma unroll
        for (int t = 0; t < 16; t++)
            v += M[s][t] * ((double)sG[t * 64 + c] / (double)srr[t]);
        g_PF2[b * 1024 + e] = (float)(v / (double)srr[s]);
    }
}

// ================= fold PF2 into conv2 proj-weights (ochalf-major) =================
__global__ __launch_bounds__(256)
void w2eff_kernel(const float* __restrict__ Wc) {
    __shared__ float sPF[1024];
    int b = blockIdx.x, tid = threadIdx.x;
    for (int i = tid; i < 1024; i += 256) sPF[i] = g_PF2[b * 1024 + i];
    __syncthreads();
    for (int e = tid; e < 9216; e += 256) {
        int tap = e / 1024, r = e & 1023, o = r >> 4, s = r & 15;
        float v = 0.f;
#pragma unroll
        for (int c = 0; c < 64; c++)
            v += Wc[o * 1152 + (64 + c) * 9 + tap] * sPF[s * 64 + c];
        __nv_bfloat16 h, l;
        split(v, h, l);
        int oh = o >> 5, ocl = o & 31;
        size_t base = (size_t)b * 18432 + (size_t)(oh * 9216 + tap * 512 + ocl * 16 + s);
        g_W2[base] = h;
        g_W2[base + 4608] = l;
    }
}

// ================= conv2: 64px strip x 32oc-half, warp tile 32px x 32oc =================
// slot layout: x-hi [0,8448), x-lo [8448,16896), U-hi [16896,19008), U-lo [19008,21120)
#define C2_WU 73728
#define C2_SLOT0 92160
#define C2_SLOTSZ 21120

__device__ __forceinline__ void c2_stage(u32 sb, int b, int x0, int ys, u32 slot, int tid) {
    bool yok = (unsigned)ys < 256u;
    int ysc = yok ? ys : 0;
    for (int i = tid; i < 1320; i += 256) {
        if (i < 1056) {
            int var = i >= 528;
            int j = i - var * 528;
            int px = j >> 3, c8 = j & 7;
            int gx = x0 - 1 + px;
            bool ok = yok && (unsigned)gx < 256u;
            int gxc = ((unsigned)gx < 256u) ? gx : 0;
            const void* src = &g_in[PLANE(var, 0, b) +
                                    (((size_t)(ysc * 256 + gxc)) << 6) + c8 * 8];
            u32 dst = sb + slot + (u32)(var * 8448 + px * 128) +
                      (u32)((c8 * 16) ^ ((px & 7) << 4));
            cpa16(dst, src, ok);
        } else {
            int j = i - 1056;
            int var = j >= 132;
            int jj = j - var * 132;
            int px = jj >> 1, hf = jj & 1;
            int gx = x0 - 1 + px;
            bool ok = yok && (unsigned)gx < 256u;
            int gxc = ((unsigned)gx < 256u) ? gx : 0;
            const __nv_bfloat16* bp = var ? g_Ul : g_Uh;
            const void* src = &bp[((size_t)b * HWN + (size_t)(ysc * 256 + gxc)) * 16 + hf * 8];
            u32 dst = sb + slot + 16896 + (u32)(var * 2112 + px * 32 + hf * 16);
            cpa16(dst, src, ok);
        }
    }
}

__global__ __launch_bounds__(256, 1)
void conv2_kernel(const float* __restrict__ x, float* __restrict__ out) {
    extern __shared__ __align__(16) unsigned char sm[];
    u32 sb = smem_u32(sm);
    int tid = threadIdx.x, lane = tid & 31, wid = tid >> 5;
    int xs = blockIdx.x & 3, oh = blockIdx.x >> 2;
    int b = blockIdx.z, y0 = blockIdx.y * 32, x0 = xs * 64;

    // weights: x 72KB (this half) + U 18KB (this half, this batch)
    for (int i = tid; i < 73728 / 16; i += 256)
        ((uint4*)sm)[i] = ((const uint4*)(g_Wc2 + oh * 73728))[i];
    for (int i = tid; i < 18432 / 16; i += 256)
        ((uint4*)(sm + C2_WU))[i] =
            ((const uint4*)((const unsigned char*)g_W2 + (size_t)b * 36864 + oh * 18432))[i];

    int i8 = lane & 7, a_mh = (lane >> 3) & 1, a_kh = lane >> 4;
    int b_kh = (lane >> 3) & 1, b_nh = lane >> 4;
    int wm = wid & 1, ym = wid >> 1;                  // 2 warps/row, 4 rows/iter
    int apx = wm * 32 + a_mh * 8 + i8;
    u32 ocw[2];
    ocw[0] = (u32)(b_nh * 8 + i8);
    ocw[1] = ocw[0] + 16;
    int g = lane >> 2, t4 = lane & 3;

    // prologue: rows y0-1 .. y0+4 into slots (r+6)%6
    for (int r = -1; r <= 4; r++)
        c2_stage(sb, b, x0, y0 + r, C2_SLOT0 + (u32)((r + 6) % 6) * C2_SLOTSZ, tid);
    CP_COMMIT();
    CP_WAIT0();
    __syncthreads();

    for (int t = 0; t < 8; t++) {
        int y = 4 * t + ym;
        int yy = y0 + y;

        float acc[2][4][4];
#pragma unroll
        for (int m = 0; m < 2; m++)
#pragma unroll
            for (int j = 0; j < 4; j++)
#pragma unroll
                for (int q = 0; q < 4; q++) acc[m][j][q] = 0.f;

#pragma unroll
        for (int ky = 0; ky < 3; ky++) {
            u32 sl = sb + C2_SLOT0 + (u32)(((y + ky - 1 + 6) % 6)) * C2_SLOTSZ;
#pragma unroll
            for (int kx = 0; kx < 3; kx++) {
                int tap = ky * 3 + kx;
                int p = apx + kx;
                u32 aoff = (u32)(p * 128);
                u32 asw = (u32)((p & 7) << 4);
                // x part: 4 k16 chunks
#pragma unroll
                for (int kc = 0; kc < 4; kc++) {
                    u32 kb = ((u32)(kc * 32 + a_kh * 16)) ^ asw;
                    u32 Ah0[4], Ah1[4], Al0[4], Al1[4];
                    ldm4(Ah0, sl + aoff + kb);
                    ldm4(Ah1, sl + aoff + 2048 + kb);
                    ldm4(Al0, sl + 8448 + aoff + kb);
                    ldm4(Al1, sl + 8448 + aoff + 2048 + kb);
                    u32 BH0[4], BH1[4], BL0[4], BL1[4];
                    u32 bcol = (u32)(kc * 32 + b_kh * 16);
                    u32 b0 = sb + (u32)(tap * 4096) + ocw[0] * 128 +
                             (bcol ^ ((ocw[0] & 7) << 4));
                    u32 b1 = sb + (u32)(tap * 4096) + ocw[1] * 128 +
                             (bcol ^ ((ocw[1] & 7) << 4));
                    ldm4(BH0, b0);
                    ldm4(BH1, b1);
                    ldm4(BL0, b0 + 36864);
                    ldm4(BL1, b1 + 36864);
#pragma unroll
                    for (int j = 0; j < 2; j++) {
                        mma16816(acc[0][j],     Ah0, BH0 + 2 * j);
                        mma16816(acc[0][j],     Al0, BH0 + 2 * j);
                        mma16816(acc[0][j],     Ah0, BL0 + 2 * j);
                        mma16816(acc[0][2 + j], Ah0, BH1 + 2 * j);
                        mma16816(acc[0][2 + j], Al0, BH1 + 2 * j);
                        mma16816(acc[0][2 + j], Ah0, BL1 + 2 * j);
                        mma16816(acc[1][j],     Ah1, BH0 + 2 * j);
                        mma16816(acc[1][j],     Al1, BH0 + 2 * j);
                        mma16816(acc[1][j],     Ah1, BL0 + 2 * j);
                        mma16816(acc[1][2 + j], Ah1, BH1 + 2 * j);
                        mma16816(acc[1][2 + j], Al1, BH1 + 2 * j);
                        mma16816(acc[1][2 + j], Ah1, BL1 + 2 * j);
                    }
                }
                // U part: single k16 (16 subspace channels)
                {
                    u32 uoff = sl + 16896 + (u32)(p * 32 + a_kh * 16);
                    u32 Ah0[4], Ah1[4], Al0[4], Al1[4];
                    ldm4(Ah0, uoff);
                    ldm4(Ah1, uoff + 512);
                    ldm4(Al0, uoff + 2112);
                    ldm4(Al1, uoff + 2112 + 512);
                    u32 BH0[4], BH1[4], BL0[4], BL1[4];
                    u32 b0 = sb + C2_WU + (u32)(tap * 1024) + ocw[0] * 32 +
                             (u32)(b_kh * 16);
                    u32 b1 = sb + C2_WU + (u32)(tap * 1024) + ocw[1] * 32 +
                             (u32)(b_kh * 16);
                    ldm4(BH0, b0);
                    ldm4(BH1, b1);
                    ldm4(BL0, b0 + 9216);
                    ldm4(BL1, b1 + 9216);
#pragma unroll
                    for (int j = 0; j < 2; j++) {
                        mma16816(acc[0][j],     Ah0, BH0 + 2 * j);
                        mma16816(acc[0][j],     Al0, BH0 + 2 * j);
                        mma16816(acc[0][j],     Ah0, BL0 + 2 * j);
                        mma16816(acc[0][2 + j], Ah0, BH1 + 2 * j);
                        mma16816(acc[0][2 + j], Al0, BH1 + 2 * j);
                        mma16816(acc[0][2 + j], Ah0, BL1 + 2 * j);
                        mma16816(acc[1][j],     Ah1, BH0 + 2 * j);
                        mma16816(acc[1][j],     Al1, BH0 + 2 * j);
                        mma16816(acc[1][j],     Ah1, BL0 + 2 * j);
                        mma16816(acc[1][2 + j], Ah1, BH1 + 2 * j);
                        mma16816(acc[1][2 + j], Al1, BH1 + 2 * j);
                        mma16816(acc[1][2 + j], Ah1, BL1 + 2 * j);
                    }
                }
            }
        }
        // writeout + residual: 32px x 32oc per warp
        size_t rowb0 = (size_t)yy * 256;
#pragma unroll
        for (int m = 0; m < 2; m++) {
            int px = x0 + wm * 32 + m * 16 + g;
            size_t rowb = rowb0 + px;
#pragma unroll
            for (int j4 = 0; j4 < 4; j4++) {
                int oc = oh * 32 + (j4 >> 1) * 16 + (j4 & 1) * 8 + 2 * t4;
                size_t o0 = ((size_t)(b * 64 + oc) << 16) + rowb;
                size_t o1 = o0 + HWN;
                out[o0] = acc[m][j4][0] + x[o0];
                out[o1] = acc[m][j4][1] + x[o1];
                out[o0 + 8] = acc[m][j4][2] + x[o0 + 8];
                out[o1 + 8] = acc[m][j4][3] + x[o1 + 8];
            }
        }

        __syncthreads();
        if (t < 7) {
#pragma unroll
            for (int r = 5; r <= 8; r++)
                c2_stage(sb, b, x0, y0 + 4 * t + r,
                         C2_SLOT0 + (u32)((4 * t + r) % 6) * C2_SLOTSZ, tid);
            CP_COMMIT();
            CP_WAIT0();
            __syncthreads();
        }
    }
}

// ================= launch =================
extern "C" void kernel_launch(void* const* d_in, const int* in_sizes, int n_in,
                              void* d_out, int out_size) {
    const float* x      = (const float*)d_in[0];
    const float* bridge = (const float*)d_in[1];
    const float* Wsub   = (const float*)d_in[2];
    const float* Wcb    = (const float*)d_in[3];
    float* out = (float*)d_out;

    cudaFuncSetAttribute(conv1_kernel, cudaFuncAttributeMaxDynamicSharedMemorySize, 208896);
    cudaFuncSetAttribute(conv2_kernel, cudaFuncAttributeMaxDynamicSharedMemorySize, 218880);

    prep_w_kernel<<<288, 256>>>(Wsub, Wcb);
    convert_kernel<<<dim3(1024, 2, 8), 256>>>(x, bridge);
    conv1_kernel<<<dim3(4, 8, 8), 256, 208896>>>();
    reduce_kernel<<<dim3(NCHUNK, BB), 256>>>(bridge);
    solve_kernel<<<BB, 256>>>();
    w2eff_kernel<<<BB, 256>>>(Wcb);
    conv2_kernel<<<dim3(8, 8, 8), 256, 218880>>>(x, out);
}

// round 11
// speedup vs baseline: 1.1990x; 1.0275x over previous
#include <cuda_runtime.h>
#include <cuda_bf16.h>
#include <cstdint>

#define BB 8
#define HWN 65536
#define NCHUNK 128
#define PART_STRIDE 1296

typedef uint32_t u32;

// ================= device scratch =================
__device__ __align__(16) __nv_bfloat16 g_in[(size_t)4 * 8 * HWN * 64];
#define PLANE(v, cg, b) (((size_t)(((v) * 2 + (cg)) * 8 + (b))) << 22)
__device__ __align__(16) float g_U[(size_t)BB * 16 * HWN];
__device__ __align__(16) __nv_bfloat16 g_Uh[(size_t)BB * HWN * 16];
__device__ __align__(16) __nv_bfloat16 g_Ul[(size_t)BB * HWN * 16];
__device__ __align__(16) float g_part[BB * NCHUNK * PART_STRIDE];
__device__ __align__(16) float g_PF2[BB * 16 * 64];
__device__ __align__(16) unsigned char g_Wc1[73728];
// conv2 x-weights, ochalf-major: [oh][var][tap][32oc][64ic] (147456 B)
__device__ __align__(16) unsigned char g_Wc2[147456];
// conv2 U-weights per batch: [b][oh][var][tap][32oc][16s] (bf16 elements)
__device__ __align__(16) __nv_bfloat16 g_W2[(size_t)BB * 18432];

// ================= helpers =================
__device__ __forceinline__ u32 smem_u32(const void* p) {
    u32 a;
    asm("{ .reg .u64 t; cvta.to.shared.u64 t, %1; cvt.u32.u64 %0, t; }" : "=r"(a) : "l"(p));
    return a;
}
__device__ __forceinline__ void ldm4(u32* r, u32 a) {
    asm volatile("ldmatrix.sync.aligned.m8n8.x4.shared.b16 {%0,%1,%2,%3}, [%4];"
                 : "=r"(r[0]), "=r"(r[1]), "=r"(r[2]), "=r"(r[3]) : "r"(a));
}
__device__ __forceinline__ void mma16816(float* c, const u32* a, const u32* b) {
    asm volatile("mma.sync.aligned.m16n8k16.row.col.f32.bf16.bf16.f32 "
                 "{%0,%1,%2,%3}, {%4,%5,%6,%7}, {%8,%9}, {%0,%1,%2,%3};"
                 : "+f"(c[0]), "+f"(c[1]), "+f"(c[2]), "+f"(c[3])
                 : "r"(a[0]), "r"(a[1]), "r"(a[2]), "r"(a[3]), "r"(b[0]), "r"(b[1]));
}
__device__ __forceinline__ void split(float f, __nv_bfloat16& h, __nv_bfloat16& l) {
    h = __float2bfloat16(f);
    l = __float2bfloat16(f - __bfloat162float(h));
}
__device__ __forceinline__ void cpa16(u32 dst, const void* src, bool pred) {
    unsigned sz = pred ? 16u : 0u;
    asm volatile("cp.async.cg.shared.global [%0], [%1], 16, %2;"
                 :: "r"(dst), "l"(__cvta_generic_to_global(src)), "r"(sz));
}
#define CP_COMMIT() asm volatile("cp.async.commit_group;" ::: "memory")
#define CP_WAIT0()  asm volatile("cp.async.wait_group 0;" ::: "memory")

// ================= weight prep =================
__global__ void prep_w_kernel(const float* __restrict__ Ws, const float* __restrict__ Wc) {
    int id = blockIdx.x * 256 + threadIdx.x;
    if (id < 64 * 1152) {
        int oc = id / 1152, rem = id - oc * 1152, ic = rem / 9, tap = rem - ic * 9;
        if (ic < 64) {
            __nv_bfloat16 h, l;
            split(Wc[id], h, l);
            int oh = oc >> 5, ocl = oc & 31;
            u32 off = (u32)(oh * 73728 + tap * 4096 + ocl * 128) +
                      (u32)((ic * 2) ^ ((ocl & 7) << 4));
            *(__nv_bfloat16*)(g_Wc2 + off) = h;
            *(__nv_bfloat16*)(g_Wc2 + off + 36864) = l;
        }
    }
    if (id < 16 * 1152) {
        int oc = id / 1152, rem = id - oc * 1152, ic = rem / 9, tap = rem - ic * 9;
        __nv_bfloat16 h, l;
        split(Ws[id], h, l);
        u32 off = (u32)((tap * 16 + oc) * 256) + (u32)((ic * 2) ^ ((oc & 7) << 4));
        *(__nv_bfloat16*)(g_Wc1 + off) = h;
        *(__nv_bfloat16*)(g_Wc1 + off + 36864) = l;
    }
}

// ================= NCHW fp32 -> NHWC bf16 hi/lo =================
__global__ __launch_bounds__(256)
void convert_kernel(const float* __restrict__ x, const float* __restrict__ bridge) {
    __shared__ float sT[64][68];
    int b = blockIdx.z, cg = blockIdx.y, pb = blockIdx.x;
    const float* src = cg ? bridge : x;
    int tid = threadIdx.x;
    int p0 = pb * 64;
    for (int i = tid; i < 64 * 64; i += 256) {
        int c = i >> 6, px = i & 63;
        sT[c][px] = src[((size_t)(b * 64 + c) << 16) + p0 + px];
    }
    __syncthreads();
    for (int i = tid; i < 512; i += 256) {
        int px = i >> 3, c8 = i & 7;
        __nv_bfloat16 hb[8], lb[8];
#pragma unroll
        for (int j = 0; j < 8; j++)
            split(sT[c8 * 8 + j][px], hb[j], lb[j]);
        size_t base = ((size_t)(p0 + px) << 6) + c8 * 8;
        *(uint4*)&g_in[PLANE(0, cg, b) + base] = *(uint4*)hb;
        *(uint4*)&g_in[PLANE(1, cg, b) + base] = *(uint4*)lb;
    }
}

// ================= conv1: 64px strip, 4 warps, warp tile 16px x 16oc x 2 rows =================
// slot planes: x-hi 0, x-lo 8448, b-hi 16896, b-lo 25344  (cg*16896 + var*8448)
#define C1_SLOT0 73728
#define C1_SLOTSZ 33792

__device__ __forceinline__ void c1_stage(u32 sb, int b, int x0, int ys, u32 slot, int tid) {
    bool yok = (unsigned)ys < 256u;
    int ysc = yok ? ys : 0;
    for (int i = tid; i < 2112; i += 128) {
        int p = i / 528, j = i - p * 528;
        int px = j >> 3, c8 = j & 7;
        int gx = x0 - 1 + px;
        bool ok = yok && (unsigned)gx < 256u;
        int gxc = ((unsigned)gx < 256u) ? gx : 0;
        const void* src = &g_in[PLANE(p & 1, p >> 1, b) +
                                (((size_t)(ysc * 256 + gxc)) << 6) + c8 * 8];
        u32 dst = sb + slot + (u32)(p * 8448 + px * 128) +
                  (u32)((c8 * 16) ^ ((px & 7) << 4));
        cpa16(dst, src, ok);
    }
}

__global__ __launch_bounds__(128, 1)
void conv1_kernel() {
    extern __shared__ __align__(16) unsigned char sm[];
    u32 sb = smem_u32(sm);
    int tid = threadIdx.x, lane = tid & 31, wid = tid >> 5;
    int b = blockIdx.z, y0 = blockIdx.y * 16, x0 = blockIdx.x * 64;

    for (int i = tid; i < 73728 / 16; i += 128)
        ((uint4*)sm)[i] = ((const uint4*)g_Wc1)[i];

    int i8 = lane & 7, a_mh = (lane >> 3) & 1, a_kh = lane >> 4;
    int b_kh = (lane >> 3) & 1, b_nh = lane >> 4;
    int wm = wid;                              // 4 m-warps x 16px
    int apx = wm * 16 + a_mh * 8 + i8;
    int ocw = b_nh * 8 + i8;                   // 16 oc rows
    u32 bRow = (u32)(ocw * 256), bx = (u32)((ocw & 7) << 4);
    int g = lane >> 2, t4 = lane & 3;

    // prologue: rows y0-1 .. y0+2 into slots 3,0,1,2
    c1_stage(sb, b, x0, y0 - 1, C1_SLOT0 + 3u * C1_SLOTSZ, tid);
    c1_stage(sb, b, x0, y0 + 0, C1_SLOT0 + 0u * C1_SLOTSZ, tid);
    c1_stage(sb, b, x0, y0 + 1, C1_SLOT0 + 1u * C1_SLOTSZ, tid);
    c1_stage(sb, b, x0, y0 + 2, C1_SLOT0 + 2u * C1_SLOTSZ, tid);
    CP_COMMIT();
    CP_WAIT0();
    __syncthreads();

    for (int t = 0; t < 8; t++) {
        float acc[2][2][4];
#pragma unroll
        for (int r = 0; r < 2; r++)
#pragma unroll
            for (int j = 0; j < 2; j++)
#pragma unroll
                for (int q = 0; q < 4; q++) acc[r][j][q] = 0.f;

#pragma unroll
        for (int ky = 0; ky < 3; ky++) {
            u32 sl0 = sb + C1_SLOT0 + (u32)(((2 * t + ky - 1) & 3)) * C1_SLOTSZ; // row 2t
            u32 sl1 = sb + C1_SLOT0 + (u32)(((2 * t + ky) & 3)) * C1_SLOTSZ;     // row 2t+1
#pragma unroll
            for (int kx = 0; kx < 3; kx++) {
                int tap = ky * 3 + kx;
                int p = apx + kx;
                u32 aoff = (u32)(p * 128);
                u32 asw = (u32)((p & 7) << 4);
#pragma unroll
                for (int cg = 0; cg < 2; cg++) {
#pragma unroll
                    for (int kc = 0; kc < 4; kc++) {
                        u32 kb = ((u32)(kc * 32 + a_kh * 16)) ^ asw;
                        u32 a0 = sl0 + (u32)(cg * 16896) + aoff + kb;
                        u32 a1 = sl1 + (u32)(cg * 16896) + aoff + kb;
                        u32 Ah0[4], Al0[4], Ah1[4], Al1[4];
                        ldm4(Ah0, a0);
                        ldm4(Al0, a0 + 8448);
                        ldm4(Ah1, a1);
                        ldm4(Al1, a1 + 8448);
                        u32 ba = sb + (u32)(tap * 4096) + bRow +
                                 (((u32)(cg * 128 + kc * 32 + b_kh * 16)) ^ bx);
                        u32 BH[4], BL[4];
                        ldm4(BH, ba);
                        ldm4(BL, ba + 36864);
#pragma unroll
                        for (int j = 0; j < 2; j++) {
                            mma16816(acc[0][j], Ah0, BH + 2 * j);
                            mma16816(acc[0][j], Al0, BH + 2 * j);
                            mma16816(acc[0][j], Ah0, BL + 2 * j);
                            mma16816(acc[1][j], Ah1, BH + 2 * j);
                            mma16816(acc[1][j], Al1, BH + 2 * j);
                            mma16816(acc[1][j], Ah1, BL + 2 * j);
                        }
                    }
                }
            }
        }
        // writeout rows 2t, 2t+1: fp32 U + bf16 hi/lo
#pragma unroll
        for (int r = 0; r < 2; r++) {
            int yy = y0 + 2 * t + r;
            int px = x0 + wm * 16 + g;
            size_t rowb = (size_t)yy * 256 + px;
#pragma unroll
            for (int j = 0; j < 2; j++) {
                int oc = j * 8 + 2 * t4;
                g_U[((size_t)(b * 16 + oc) << 16) + rowb] = acc[r][j][0];
                g_U[((size_t)(b * 16 + oc + 1) << 16) + rowb] = acc[r][j][1];
                g_U[((size_t)(b * 16 + oc) << 16) + rowb + 8] = acc[r][j][2];
                g_U[((size_t)(b * 16 + oc + 1) << 16) + rowb + 8] = acc[r][j][3];
                __nv_bfloat16 h0, l0, h1, l1;
                split(acc[r][j][0], h0, l0);
                split(acc[r][j][1], h1, l1);
                size_t idx = ((size_t)b * HWN + rowb) * 16 + oc;
                __nv_bfloat162 hh, ll;
                hh.x = h0; hh.y = h1; ll.x = l0; ll.y = l1;
                *(__nv_bfloat162*)&g_Uh[idx] = hh;
                *(__nv_bfloat162*)&g_Ul[idx] = ll;
                split(acc[r][j][2], h0, l0);
                split(acc[r][j][3], h1, l1);
                hh.x = h0; hh.y = h1; ll.x = l0; ll.y = l1;
                *(__nv_bfloat162*)&g_Uh[idx + 128] = hh;
                *(__nv_bfloat162*)&g_Ul[idx + 128] = ll;
            }
        }

        __syncthreads();
        if (t < 7) {
            c1_stage(sb, b, x0, y0 + 2 * t + 3,
                     C1_SLOT0 + (u32)((2 * t + 3) & 3) * C1_SLOTSZ, tid);
            c1_stage(sb, b, x0, y0 + 2 * t + 4,
                     C1_SLOT0 + (u32)((2 * t + 4) & 3) * C1_SLOTSZ, tid);
            CP_COMMIT();
            CP_WAIT0();
            __syncthreads();
        }
    }
}

// ================= reduction (fp32, unchanged) =================
__global__ __launch_bounds__(256)
void reduce_kernel(const float* __restrict__ bridge) {
    __shared__ __align__(16) float sU[16][68];
    __shared__ __align__(16) float sB[64][68];
    int b = blockIdx.y, ch = blockIdx.x;
    int tid = threadIdx.x;
    int s = tid >> 4, q = tid & 15;
    int n0 = ch * 512;
    const float* Ub = g_U + (size_t)b * 16 * HWN;
    const float* Bb = bridge + (size_t)b * 64 * HWN;
    float accG[4] = {0.f, 0.f, 0.f, 0.f};
    float accM = 0.f, accR = 0.f;
    for (int sub = 0; sub < 8; sub++) {
        int n = n0 + sub * 64;
        {
            int sl = tid >> 4, p4 = (tid & 15) * 4;
            *reinterpret_cast<float4*>(&sU[sl][p4]) =
                *reinterpret_cast<const float4*>(&Ub[sl * HWN + n + p4]);
        }
#pragma unroll
        for (int r = 0; r < 4; r++) {
            int cl = (tid >> 4) + r * 16;
            int p4 = (tid & 15) * 4;
            *reinterpret_cast<float4*>(&sB[cl][p4]) =
                *reinterpret_cast<const float4*>(&Bb[cl * HWN + n + p4]);
        }
        __syncthreads();
#pragma unroll
        for (int p = 0; p < 64; p += 4) {
            float4 u = *reinterpret_cast<float4*>(&sU[s][p]);
            float4 t4 = *reinterpret_cast<float4*>(&sU[q][p]);
            accM += u.x * t4.x + u.y * t4.y + u.z * t4.z + u.w * t4.w;
#pragma unroll
            for (int j = 0; j < 4; j++) {
                float4 bv = *reinterpret_cast<float4*>(&sB[q + j * 16][p]);
                accG[j] += u.x * bv.x + u.y * bv.y + u.z * bv.z + u.w * bv.w;
            }
            if (q == 0) accR += fabsf(u.x) + fabsf(u.y) + fabsf(u.z) + fabsf(u.w);
        }
        __syncthreads();
    }
    float* o = g_part + (size_t)(b * NCHUNK + ch) * PART_STRIDE;
    o[s * 16 + q] = accM;
#pragma unroll
    for (int j = 0; j < 4; j++) o[256 + s * 64 + q + j * 16] = accG[j];
    if (q == 0) o[1280 + s] = accR;
}

// ================= solve (unchanged) =================
__global__ __launch_bounds__(256)
void solve_kernel() {
    __shared__ float sGram[256];
    __shared__ float sG[1024];
    __shared__ float srr[16];
    __shared__ double A[16][17];
    __shared__ double M[16][17];
    __shared__ double spiv;
    int b = blockIdx.x;
    int tid = threadIdx.x;
    const float* base = g_part + (size_t)b * NCHUNK * PART_STRIDE;
    {
        float a = 0.f;
        for (int ch = 0; ch < NCHUNK; ch++) a += base[ch * PART_STRIDE + tid];
        sGram[tid] = a;
    }
#pragma unroll
    for (int j = 0; j < 4; j++) {
        int e = tid + j * 256;
        float a = 0.f;
        for (int ch = 0; ch < NCHUNK; ch++) a += base[ch * PART_STRIDE + 256 + e];
        sG[e] = a;
    }
    if (tid < 16) {
        float a = 0.f;
        for (int ch = 0; ch < NCHUNK; ch++) a += base[ch * PART_STRIDE + 1280 + tid];
        srr[tid] = 1e-6f + a;
    }
    __syncthreads();
    {
        int i = tid >> 4, t = tid & 15;
        A[i][t] = (double)sGram[tid] / ((double)srr[i] * (double)srr[t]);
        M[i][t] = (i == t) ? 1.0 : 0.0;
    }
    __syncthreads();
    for (int k = 0; k < 16; k++) {
        if (tid == 0) spiv = 1.0 / A[k][k];
        __syncthreads();
        if (tid < 16) { A[k][tid] *= spiv; M[k][tid] *= spiv; }
        __syncthreads();
        int i = tid >> 4, t = tid & 15;
        double f = A[i][k];
        __syncthreads();
        if (i != k) { A[i][t] -= f * A[k][t]; M[i][t] -= f * M[k][t]; }
        __syncthreads();
    }
#pragma unroll
    for (int j = 0; j < 4; j++) {
        int e = tid + j * 256;
        int s = e >> 6, c = e & 63;
        double v = 0.0;
#pragma unroll
        for (int t = 0; t < 16; t++)
            v += M[s][t] * ((double)sG[t * 64 + c] / (double)srr[t]);
        g_PF2[b * 1024 + e] = (float)(v / (double)srr[s]);
    }
}

// ================= fold PF2 into conv2 proj-weights (ochalf-major) =================
__global__ __launch_bounds__(256)
void w2eff_kernel(const float* __restrict__ Wc) {
    __shared__ float sPF[1024];
    int b = blockIdx.x, tid = threadIdx.x;
    for (int i = tid; i < 1024; i += 256) sPF[i] = g_PF2[b * 1024 + i];
    __syncthreads();
    for (int e = tid; e < 9216; e += 256) {
        int tap = e / 1024, r = e & 1023, o = r >> 4, s = r & 15;
        float v = 0.f;
#pragma unroll
        for (int c = 0; c < 64; c++)
            v += Wc[o * 1152 + (64 + c) * 9 + tap] * sPF[s * 64 + c];
        __nv_bfloat16 h, l;
        split(v, h, l);
        int oh = o >> 5, ocl = o & 31;
        size_t base = (size_t)b * 18432 + (size_t)(oh * 9216 + tap * 512 + ocl * 16 + s);
        g_W2[base] = h;
        g_W2[base + 4608] = l;
    }
}

// ================= conv2: 64px strip x 32oc-half, warp tile 32px x 32oc =================
// slot layout: x-hi [0,8448), x-lo [8448,16896), U-hi [16896,19008), U-lo [19008,21120)
#define C2_WU 73728
#define C2_SLOT0 92160
#define C2_SLOTSZ 21120

__device__ __forceinline__ void c2_stage(u32 sb, int b, int x0, int ys, u32 slot, int tid) {
    bool yok = (unsigned)ys < 256u;
    int ysc = yok ? ys : 0;
    for (int i = tid; i < 1320; i += 256) {
        if (i < 1056) {
            int var = i >= 528;
            int j = i - var * 528;
            int px = j >> 3, c8 = j & 7;
            int gx = x0 - 1 + px;
            bool ok = yok && (unsigned)gx < 256u;
            int gxc = ((unsigned)gx < 256u) ? gx : 0;
            const void* src = &g_in[PLANE(var, 0, b) +
                                    (((size_t)(ysc * 256 + gxc)) << 6) + c8 * 8];
            u32 dst = sb + slot + (u32)(var * 8448 + px * 128) +
                      (u32)((c8 * 16) ^ ((px & 7) << 4));
            cpa16(dst, src, ok);
        } else {
            int j = i - 1056;
            int var = j >= 132;
            int jj = j - var * 132;
            int px = jj >> 1, hf = jj & 1;
            int gx = x0 - 1 + px;
            bool ok = yok && (unsigned)gx < 256u;
            int gxc = ((unsigned)gx < 256u) ? gx : 0;
            const __nv_bfloat16* bp = var ? g_Ul : g_Uh;
            const void* src = &bp[((size_t)b * HWN + (size_t)(ysc * 256 + gxc)) * 16 + hf * 8];
            u32 dst = sb + slot + 16896 + (u32)(var * 2112 + px * 32 + hf * 16);
            cpa16(dst, src, ok);
        }
    }
}

__global__ __launch_bounds__(256, 1)
void conv2_kernel(const float* __restrict__ x, float* __restrict__ out) {
    extern __shared__ __align__(16) unsigned char sm[];
    u32 sb = smem_u32(sm);
    int tid = threadIdx.x, lane = tid & 31, wid = tid >> 5;
    int xs = blockIdx.x & 3, oh = blockIdx.x >> 2;
    int b = blockIdx.z, y0 = blockIdx.y * 32, x0 = xs * 64;

    // weights: x 72KB (this half) + U 18KB (this half, this batch)
    for (int i = tid; i < 73728 / 16; i += 256)
        ((uint4*)sm)[i] = ((const uint4*)(g_Wc2 + oh * 73728))[i];
    for (int i = tid; i < 18432 / 16; i += 256)
        ((uint4*)(sm + C2_WU))[i] =
            ((const uint4*)((const unsigned char*)g_W2 + (size_t)b * 36864 + oh * 18432))[i];

    int i8 = lane & 7, a_mh = (lane >> 3) & 1, a_kh = lane >> 4;
    int b_kh = (lane >> 3) & 1, b_nh = lane >> 4;
    int wm = wid & 1, ym = wid >> 1;                  // 2 warps/row, 4 rows/iter
    int apx = wm * 32 + a_mh * 8 + i8;
    u32 ocw[2];
    ocw[0] = (u32)(b_nh * 8 + i8);
    ocw[1] = ocw[0] + 16;
    int g = lane >> 2, t4 = lane & 3;

    // prologue: rows y0-1 .. y0+4 into slots (r+6)%6
    for (int r = -1; r <= 4; r++)
        c2_stage(sb, b, x0, y0 + r, C2_SLOT0 + (u32)((r + 6) % 6) * C2_SLOTSZ, tid);
    CP_COMMIT();
    CP_WAIT0();
    __syncthreads();

    for (int t = 0; t < 8; t++) {
        int y = 4 * t + ym;
        int yy = y0 + y;

        float acc[2][4][4];
#pragma unroll
        for (int m = 0; m < 2; m++)
#pragma unroll
            for (int j = 0; j < 4; j++)
#pragma unroll
                for (int q = 0; q < 4; q++) acc[m][j][q] = 0.f;

#pragma unroll
        for (int ky = 0; ky < 3; ky++) {
            u32 sl = sb + C2_SLOT0 + (u32)(((y + ky - 1 + 6) % 6)) * C2_SLOTSZ;
#pragma unroll
            for (int kx = 0; kx < 3; kx++) {
                int tap = ky * 3 + kx;
                int p = apx + kx;
                u32 aoff = (u32)(p * 128);
                u32 asw = (u32)((p & 7) << 4);
                // x part: 4 k16 chunks
#pragma unroll
                for (int kc = 0; kc < 4; kc++) {
                    u32 kb = ((u32)(kc * 32 + a_kh * 16)) ^ asw;
                    u32 Ah0[4], Ah1[4], Al0[4], Al1[4];
                    ldm4(Ah0, sl + aoff + kb);
                    ldm4(Ah1, sl + aoff + 2048 + kb);
                    ldm4(Al0, sl + 8448 + aoff + kb);
                    ldm4(Al1, sl + 8448 + aoff + 2048 + kb);
                    u32 BH0[4], BH1[4], BL0[4], BL1[4];
                    u32 bcol = (u32)(kc * 32 + b_kh * 16);
                    u32 b0 = sb + (u32)(tap * 4096) + ocw[0] * 128 +
                             (bcol ^ ((ocw[0] & 7) << 4));
                    u32 b1 = sb + (u32)(tap * 4096) + ocw[1] * 128 +
                             (bcol ^ ((ocw[1] & 7) << 4));
                    ldm4(BH0, b0);
                    ldm4(BH1, b1);
                    ldm4(BL0, b0 + 36864);
                    ldm4(BL1, b1 + 36864);
#pragma unroll
                    for (int j = 0; j < 2; j++) {
                        mma16816(acc[0][j],     Ah0, BH0 + 2 * j);
                        mma16816(acc[0][j],     Al0, BH0 + 2 * j);
                        mma16816(acc[0][j],     Ah0, BL0 + 2 * j);
                        mma16816(acc[0][2 + j], Ah0, BH1 + 2 * j);
                        mma16816(acc[0][2 + j], Al0, BH1 + 2 * j);
                        mma16816(acc[0][2 + j], Ah0, BL1 + 2 * j);
                        mma16816(acc[1][j],     Ah1, BH0 + 2 * j);
                        mma16816(acc[1][j],     Al1, BH0 + 2 * j);
                        mma16816(acc[1][j],     Ah1, BL0 + 2 * j);
                        mma16816(acc[1][2 + j], Ah1, BH1 + 2 * j);
                        mma16816(acc[1][2 + j], Al1, BH1 + 2 * j);
                        mma16816(acc[1][2 + j], Ah1, BL1 + 2 * j);
                    }
                }
                // U part: single k16 (16 subspace channels)
                {
                    u32 uoff = sl + 16896 + (u32)(p * 32 + a_kh * 16);
                    u32 Ah0[4], Ah1[4], Al0[4], Al1[4];
                    ldm4(Ah0, uoff);
                    ldm4(Ah1, uoff + 512);
                    ldm4(Al0, uoff + 2112);
                    ldm4(Al1, uoff + 2112 + 512);
                    u32 BH0[4], BH1[4], BL0[4], BL1[4];
                    u32 b0 = sb + C2_WU + (u32)(tap * 1024) + ocw[0] * 32 +
                             (u32)(b_kh * 16);
                    u32 b1 = sb + C2_WU + (u32)(tap * 1024) + ocw[1] * 32 +
                             (u32)(b_kh * 16);
                    ldm4(BH0, b0);
                    ldm4(BH1, b1);
                    ldm4(BL0, b0 + 9216);
                    ldm4(BL1, b1 + 9216);
#pragma unroll
                    for (int j = 0; j < 2; j++) {
                        mma16816(acc[0][j],     Ah0, BH0 + 2 * j);
                        mma16816(acc[0][j],     Al0, BH0 + 2 * j);
                        mma16816(acc[0][j],     Ah0, BL0 + 2 * j);
                        mma16816(acc[0][2 + j], Ah0, BH1 + 2 * j);
                        mma16816(acc[0][2 + j], Al0, BH1 + 2 * j);
                        mma16816(acc[0][2 + j], Ah0, BL1 + 2 * j);
                        mma16816(acc[1][j],     Ah1, BH0 + 2 * j);
                        mma16816(acc[1][j],     Al1, BH0 + 2 * j);
                        mma16816(acc[1][j],     Ah1, BL0 + 2 * j);
                        mma16816(acc[1][2 + j], Ah1, BH1 + 2 * j);
                        mma16816(acc[1][2 + j], Al1, BH1 + 2 * j);
                        mma16816(acc[1][2 + j], Ah1, BL1 + 2 * j);
                    }
                }
            }
        }
        // writeout + residual: 32px x 32oc per warp
        size_t rowb0 = (size_t)yy * 256;
#pragma unroll
        for (int m = 0; m < 2; m++) {
            int px = x0 + wm * 32 + m * 16 + g;
            size_t rowb = rowb0 + px;
#pragma unroll
            for (int j4 = 0; j4 < 4; j4++) {
                int oc = oh * 32 + (j4 >> 1) * 16 + (j4 & 1) * 8 + 2 * t4;
                size_t o0 = ((size_t)(b * 64 + oc) << 16) + rowb;
                size_t o1 = o0 + HWN;
                out[o0] = acc[m][j4][0] + x[o0];
                out[o1] = acc[m][j4][1] + x[o1];
                out[o0 + 8] = acc[m][j4][2] + x[o0 + 8];
                out[o1 + 8] = acc[m][j4][3] + x[o1 + 8];
            }
        }

        __syncthreads();
        if (t < 7) {
#pragma unroll
            for (int r = 5; r <= 8; r++)
                c2_stage(sb, b, x0, y0 + 4 * t + r,
                         C2_SLOT0 + (u32)((4 * t + r) % 6) * C2_SLOTSZ, tid);
            CP_COMMIT();
            CP_WAIT0();
            __syncthreads();
        }
    }
}

// ================= launch =================
extern "C" void kernel_launch(void* const* d_in, const int* in_sizes, int n_in,
                              void* d_out, int out_size) {
    const float* x      = (const float*)d_in[0];
    const float* bridge = (const float*)d_in[1];
    const float* Wsub   = (const float*)d_in[2];
    const float* Wcb    = (const float*)d_in[3];
    float* out = (float*)d_out;

    cudaFuncSetAttribute(conv1_kernel, cudaFuncAttributeMaxDynamicSharedMemorySize, 208896);
    cudaFuncSetAttribute(conv2_kernel, cudaFuncAttributeMaxDynamicSharedMemorySize, 218880);

    prep_w_kernel<<<288, 256>>>(Wsub, Wcb);
    convert_kernel<<<dim3(1024, 2, 8), 256>>>(x, bridge);
    conv1_kernel<<<dim3(4, 16, 8), 128, 208896>>>();
    reduce_kernel<<<dim3(NCHUNK, BB), 256>>>(bridge);
    solve_kernel<<<BB, 256>>>();
    w2eff_kernel<<<BB, 256>>>(Wcb);
    conv2_kernel<<<dim3(8, 8, 8), 256, 218880>>>(x, out);
}

// round 12
// speedup vs baseline: 1.4255x; 1.1889x over previous
#include <cuda_runtime.h>
#include <cuda_fp16.h>
#include <cstdint>

#define BB 8
#define HWN 65536
#define NCHUNK 128
#define PART_STRIDE 1296

typedef uint32_t u32;

// ================= device scratch =================
// NHWC fp16 planes: [v(hi/lo)][cg(0:x,1:bridge)][b][pixel][64ch]
__device__ __align__(16) __half g_in[(size_t)4 * 8 * HWN * 64];
#define PLANE(v, cg, b) (((size_t)(((v) * 2 + (cg)) * 8 + (b))) << 22)
__device__ __align__(16) float g_U[(size_t)BB * 16 * HWN];
__device__ __align__(16) __half g_Uh[(size_t)BB * HWN * 16];
__device__ __align__(16) __half g_Ul[(size_t)BB * HWN * 16];
__device__ __align__(16) float g_part[BB * NCHUNK * PART_STRIDE];
__device__ __align__(16) float g_PF2[BB * 16 * 64];
// conv1 weights fp16: [tap][16oc][128ic] = 36864 B
__device__ __align__(16) unsigned char g_Wc1[36864];
// conv2 x-weights fp16, ochalf-major: [oh][tap][32oc][64ic] = 73728 B
__device__ __align__(16) unsigned char g_Wc2[73728];
// conv2 U-weights fp16 per batch: [b][oh][tap][32oc][16s]
__device__ __align__(16) __half g_W2[(size_t)BB * 9216];

// ================= helpers =================
__device__ __forceinline__ u32 smem_u32(const void* p) {
    u32 a;
    asm("{ .reg .u64 t; cvta.to.shared.u64 t, %1; cvt.u32.u64 %0, t; }" : "=r"(a) : "l"(p));
    return a;
}
__device__ __forceinline__ void ldm4(u32* r, u32 a) {
    asm volatile("ldmatrix.sync.aligned.m8n8.x4.shared.b16 {%0,%1,%2,%3}, [%4];"
                 : "=r"(r[0]), "=r"(r[1]), "=r"(r[2]), "=r"(r[3]) : "r"(a));
}
__device__ __forceinline__ void mma16816(float* c, const u32* a, const u32* b) {
    asm volatile("mma.sync.aligned.m16n8k16.row.col.f32.f16.f16.f32 "
                 "{%0,%1,%2,%3}, {%4,%5,%6,%7}, {%8,%9}, {%0,%1,%2,%3};"
                 : "+f"(c[0]), "+f"(c[1]), "+f"(c[2]), "+f"(c[3])
                 : "r"(a[0]), "r"(a[1]), "r"(a[2]), "r"(a[3]), "r"(b[0]), "r"(b[1]));
}
__device__ __forceinline__ void splith(float f, __half& h, __half& l) {
    h = __float2half(f);
    l = __float2half(f - __half2float(h));
}
__device__ __forceinline__ void cpa16(u32 dst, const void* src, bool pred) {
    unsigned sz = pred ? 16u : 0u;
    asm volatile("cp.async.cg.shared.global [%0], [%1], 16, %2;"
                 :: "r"(dst), "l"(__cvta_generic_to_global(src)), "r"(sz));
}
#define CP_COMMIT() asm volatile("cp.async.commit_group;" ::: "memory")
#define CP_WAIT0()  asm volatile("cp.async.wait_group 0;" ::: "memory")

// ================= weight prep (single fp16) =================
__global__ void prep_w_kernel(const float* __restrict__ Ws, const float* __restrict__ Wc) {
    int id = blockIdx.x * 256 + threadIdx.x;
    if (id < 64 * 1152) {
        int oc = id / 1152, rem = id - oc * 1152, ic = rem / 9, tap = rem - ic * 9;
        if (ic < 64) {
            int oh = oc >> 5, ocl = oc & 31;
            u32 off = (u32)(oh * 36864 + tap * 4096 + ocl * 128) +
                      (u32)((ic * 2) ^ ((ocl & 7) << 4));
            *(__half*)(g_Wc2 + off) = __float2half(Wc[id]);
        }
    }
    if (id < 16 * 1152) {
        int oc = id / 1152, rem = id - oc * 1152, ic = rem / 9, tap = rem - ic * 9;
        u32 off = (u32)((tap * 16 + oc) * 256) + (u32)((ic * 2) ^ ((oc & 7) << 4));
        *(__half*)(g_Wc1 + off) = __float2half(Ws[id]);
    }
}

// ================= NCHW fp32 -> NHWC fp16 hi/lo =================
__global__ __launch_bounds__(256)
void convert_kernel(const float* __restrict__ x, const float* __restrict__ bridge) {
    __shared__ float sT[64][68];
    int b = blockIdx.z, cg = blockIdx.y, pb = blockIdx.x;
    const float* src = cg ? bridge : x;
    int tid = threadIdx.x;
    int p0 = pb * 64;
    for (int i = tid; i < 64 * 64; i += 256) {
        int c = i >> 6, px = i & 63;
        sT[c][px] = src[((size_t)(b * 64 + c) << 16) + p0 + px];
    }
    __syncthreads();
    for (int i = tid; i < 512; i += 256) {
        int px = i >> 3, c8 = i & 7;
        __half hb[8], lb[8];
#pragma unroll
        for (int j = 0; j < 8; j++)
            splith(sT[c8 * 8 + j][px], hb[j], lb[j]);
        size_t base = ((size_t)(p0 + px) << 6) + c8 * 8;
        *(uint4*)&g_in[PLANE(0, cg, b) + base] = *(uint4*)hb;
        *(uint4*)&g_in[PLANE(1, cg, b) + base] = *(uint4*)lb;
    }
}

// ================= conv1: 64px strip, 4 warps, warp tile 16px x 16oc x 2 rows =================
// slot planes: x-hi 0, x-lo 8448, b-hi 16896, b-lo 25344  (cg*16896 + var*8448)
#define C1_SLOT0 36864
#define C1_SLOTSZ 33792

__device__ __forceinline__ void c1_stage(u32 sb, int b, int x0, int ys, u32 slot, int tid) {
    bool yok = (unsigned)ys < 256u;
    int ysc = yok ? ys : 0;
    for (int i = tid; i < 2112; i += 128) {
        int p = i / 528, j = i - p * 528;
        int px = j >> 3, c8 = j & 7;
        int gx = x0 - 1 + px;
        bool ok = yok && (unsigned)gx < 256u;
        int gxc = ((unsigned)gx < 256u) ? gx : 0;
        const void* src = &g_in[PLANE(p & 1, p >> 1, b) +
                                (((size_t)(ysc * 256 + gxc)) << 6) + c8 * 8];
        u32 dst = sb + slot + (u32)(p * 8448 + px * 128) +
                  (u32)((c8 * 16) ^ ((px & 7) << 4));
        cpa16(dst, src, ok);
    }
}

__global__ __launch_bounds__(128, 1)
void conv1_kernel() {
    extern __shared__ __align__(16) unsigned char sm[];
    u32 sb = smem_u32(sm);
    int tid = threadIdx.x, lane = tid & 31, wid = tid >> 5;
    int b = blockIdx.z, y0 = blockIdx.y * 16, x0 = blockIdx.x * 64;

    for (int i = tid; i < 36864 / 16; i += 128)
        ((uint4*)sm)[i] = ((const uint4*)g_Wc1)[i];

    int i8 = lane & 7, a_mh = (lane >> 3) & 1, a_kh = lane >> 4;
    int b_kh = (lane >> 3) & 1, b_nh = lane >> 4;
    int wm = wid;                              // 4 m-warps x 16px
    int apx = wm * 16 + a_mh * 8 + i8;
    int ocw = b_nh * 8 + i8;                   // 16 oc rows
    u32 bRow = (u32)(ocw * 256), bx = (u32)((ocw & 7) << 4);
    int g = lane >> 2, t4 = lane & 3;

    // prologue: rows y0-1 .. y0+2 into slots 3,0,1,2
    c1_stage(sb, b, x0, y0 - 1, C1_SLOT0 + 3u * C1_SLOTSZ, tid);
    c1_stage(sb, b, x0, y0 + 0, C1_SLOT0 + 0u * C1_SLOTSZ, tid);
    c1_stage(sb, b, x0, y0 + 1, C1_SLOT0 + 1u * C1_SLOTSZ, tid);
    c1_stage(sb, b, x0, y0 + 2, C1_SLOT0 + 2u * C1_SLOTSZ, tid);
    CP_COMMIT();
    CP_WAIT0();
    __syncthreads();

    for (int t = 0; t < 8; t++) {
        float acc[2][2][4];
#pragma unroll
        for (int r = 0; r < 2; r++)
#pragma unroll
            for (int j = 0; j < 2; j++)
#pragma unroll
                for (int q = 0; q < 4; q++) acc[r][j][q] = 0.f;

#pragma unroll
        for (int ky = 0; ky < 3; ky++) {
            u32 sl0 = sb + C1_SLOT0 + (u32)(((2 * t + ky - 1) & 3)) * C1_SLOTSZ; // row 2t
            u32 sl1 = sb + C1_SLOT0 + (u32)(((2 * t + ky) & 3)) * C1_SLOTSZ;     // row 2t+1
#pragma unroll
            for (int kx = 0; kx < 3; kx++) {
                int tap = ky * 3 + kx;
                int p = apx + kx;
                u32 aoff = (u32)(p * 128);
                u32 asw = (u32)((p & 7) << 4);
#pragma unroll
                for (int cg = 0; cg < 2; cg++) {
#pragma unroll
                    for (int kc = 0; kc < 4; kc++) {
                        u32 kb = ((u32)(kc * 32 + a_kh * 16)) ^ asw;
                        u32 a0 = sl0 + (u32)(cg * 16896) + aoff + kb;
                        u32 a1 = sl1 + (u32)(cg * 16896) + aoff + kb;
                        u32 Ah0[4], Al0[4], Ah1[4], Al1[4];
                        ldm4(Ah0, a0);
                        ldm4(Al0, a0 + 8448);
                        ldm4(Ah1, a1);
                        ldm4(Al1, a1 + 8448);
                        u32 ba = sb + (u32)(tap * 4096) + bRow +
                                 (((u32)(cg * 128 + kc * 32 + b_kh * 16)) ^ bx);
                        u32 BH[4];
                        ldm4(BH, ba);
#pragma unroll
                        for (int j = 0; j < 2; j++) {
                            mma16816(acc[0][j], Ah0, BH + 2 * j);
                            mma16816(acc[0][j], Al0, BH + 2 * j);
                            mma16816(acc[1][j], Ah1, BH + 2 * j);
                            mma16816(acc[1][j], Al1, BH + 2 * j);
                        }
                    }
                }
            }
        }
        // writeout rows 2t, 2t+1: fp32 U + fp16 hi/lo
#pragma unroll
        for (int r = 0; r < 2; r++) {
            int yy = y0 + 2 * t + r;
            int px = x0 + wm * 16 + g;
            size_t rowb = (size_t)yy * 256 + px;
#pragma unroll
            for (int j = 0; j < 2; j++) {
                int oc = j * 8 + 2 * t4;
                g_U[((size_t)(b * 16 + oc) << 16) + rowb] = acc[r][j][0];
                g_U[((size_t)(b * 16 + oc + 1) << 16) + rowb] = acc[r][j][1];
                g_U[((size_t)(b * 16 + oc) << 16) + rowb + 8] = acc[r][j][2];
                g_U[((size_t)(b * 16 + oc + 1) << 16) + rowb + 8] = acc[r][j][3];
                __half h0, l0, h1, l1;
                splith(acc[r][j][0], h0, l0);
                splith(acc[r][j][1], h1, l1);
                size_t idx = ((size_t)b * HWN + rowb) * 16 + oc;
                __half2 hh, ll;
                hh.x = h0; hh.y = h1; ll.x = l0; ll.y = l1;
                *(__half2*)&g_Uh[idx] = hh;
                *(__half2*)&g_Ul[idx] = ll;
                splith(acc[r][j][2], h0, l0);
                splith(acc[r][j][3], h1, l1);
                hh.x = h0; hh.y = h1; ll.x = l0; ll.y = l1;
                *(__half2*)&g_Uh[idx + 128] = hh;
                *(__half2*)&g_Ul[idx + 128] = ll;
            }
        }

        __syncthreads();
        if (t < 7) {
            c1_stage(sb, b, x0, y0 + 2 * t + 3,
                     C1_SLOT0 + (u32)((2 * t + 3) & 3) * C1_SLOTSZ, tid);
            c1_stage(sb, b, x0, y0 + 2 * t + 4,
                     C1_SLOT0 + (u32)((2 * t + 4) & 3) * C1_SLOTSZ, tid);
            CP_COMMIT();
            CP_WAIT0();
            __syncthreads();
        }
    }
}

// ================= reduction (fp32, unchanged) =================
__global__ __launch_bounds__(256)
void reduce_kernel(const float* __restrict__ bridge) {
    __shared__ __align__(16) float sU[16][68];
    __shared__ __align__(16) float sB[64][68];
    int b = blockIdx.y, ch = blockIdx.x;
    int tid = threadIdx.x;
    int s = tid >> 4, q = tid & 15;
    int n0 = ch * 512;
    const float* Ub = g_U + (size_t)b * 16 * HWN;
    const float* Bb = bridge + (size_t)b * 64 * HWN;
    float accG[4] = {0.f, 0.f, 0.f, 0.f};
    float accM = 0.f, accR = 0.f;
    for (int sub = 0; sub < 8; sub++) {
        int n = n0 + sub * 64;
        {
            int sl = tid >> 4, p4 = (tid & 15) * 4;
            *reinterpret_cast<float4*>(&sU[sl][p4]) =
                *reinterpret_cast<const float4*>(&Ub[sl * HWN + n + p4]);
        }
#pragma unroll
        for (int r = 0; r < 4; r++) {
            int cl = (tid >> 4) + r * 16;
            int p4 = (tid & 15) * 4;
            *reinterpret_cast<float4*>(&sB[cl][p4]) =
                *reinterpret_cast<const float4*>(&Bb[cl * HWN + n + p4]);
        }
        __syncthreads();
#pragma unroll
        for (int p = 0; p < 64; p += 4) {
            float4 u = *reinterpret_cast<float4*>(&sU[s][p]);
            float4 t4 = *reinterpret_cast<float4*>(&sU[q][p]);
            accM += u.x * t4.x + u.y * t4.y + u.z * t4.z + u.w * t4.w;
#pragma unroll
            for (int j = 0; j < 4; j++) {
                float4 bv = *reinterpret_cast<float4*>(&sB[q + j * 16][p]);
                accG[j] += u.x * bv.x + u.y * bv.y + u.z * bv.z + u.w * bv.w;
            }
            if (q == 0) accR += fabsf(u.x) + fabsf(u.y) + fabsf(u.z) + fabsf(u.w);
        }
        __syncthreads();
    }
    float* o = g_part + (size_t)(b * NCHUNK + ch) * PART_STRIDE;
    o[s * 16 + q] = accM;
#pragma unroll
    for (int j = 0; j < 4; j++) o[256 + s * 64 + q + j * 16] = accG[j];
    if (q == 0) o[1280 + s] = accR;
}

// ================= solve (unchanged) =================
__global__ __launch_bounds__(256)
void solve_kernel() {
    __shared__ float sGram[256];
    __shared__ float sG[1024];
    __shared__ float srr[16];
    __shared__ double A[16][17];
    __shared__ double M[16][17];
    __shared__ double spiv;
    int b = blockIdx.x;
    int tid = threadIdx.x;
    const float* base = g_part + (size_t)b * NCHUNK * PART_STRIDE;
    {
        float a = 0.f;
        for (int ch = 0; ch < NCHUNK; ch++) a += base[ch * PART_STRIDE + tid];
        sGram[tid] = a;
    }
#pragma unroll
    for (int j = 0; j < 4; j++) {
        int e = tid + j * 256;
        float a = 0.f;
        for (int ch = 0; ch < NCHUNK; ch++) a += base[ch * PART_STRIDE + 256 + e];
        sG[e] = a;
    }
    if (tid < 16) {
        float a = 0.f;
        for (int ch = 0; ch < NCHUNK; ch++) a += base[ch * PART_STRIDE + 1280 + tid];
        srr[tid] = 1e-6f + a;
    }
    __syncthreads();
    {
        int i = tid >> 4, t = tid & 15;
        A[i][t] = (double)sGram[tid] / ((double)srr[i] * (double)srr[t]);
        M[i][t] = (i == t) ? 1.0 : 0.0;
    }
    __syncthreads();
    for (int k = 0; k < 16; k++) {
        if (tid == 0) spiv = 1.0 / A[k][k];
        __syncthreads();
        if (tid < 16) { A[k][tid] *= spiv; M[k][tid] *= spiv; }
        __syncthreads();
        int i = tid >> 4, t = tid & 15;
        double f = A[i][k];
        __syncthreads();
        if (i != k) { A[i][t] -= f * A[k][t]; M[i][t] -= f * M[k][t]; }
        __syncthreads();
    }
#pragma unroll
    for (int j = 0; j < 4; j++) {
        int e = tid + j * 256;
        int s = e >> 6, c = e & 63;
        double v = 0.0;
#pragma unroll
        for (int t = 0; t < 16; t++)
            v += M[s][t] * ((double)sG[t * 64 + c] / (double)srr[t]);
        g_PF2[b * 1024 + e] = (float)(v / (double)srr[s]);
    }
}

// ================= fold PF2 into conv2 proj-weights (fp16, ochalf-major) =================
__global__ __launch_bounds__(256)
void w2eff_kernel(const float* __restrict__ Wc) {
    __shared__ float sPF[1024];
    int b = blockIdx.x, tid = threadIdx.x;
    for (int i = tid; i < 1024; i += 256) sPF[i] = g_PF2[b * 1024 + i];
    __syncthreads();
    for (int e = tid; e < 9216; e += 256) {
        int tap = e / 1024, r = e & 1023, o = r >> 4, s = r & 15;
        float v = 0.f;
#pragma unroll
        for (int c = 0; c < 64; c++)
            v += Wc[o * 1152 + (64 + c) * 9 + tap] * sPF[s * 64 + c];
        int oh = o >> 5, ocl = o & 31;
        g_W2[(size_t)b * 9216 + (size_t)(oh * 4608 + tap * 512 + ocl * 16 + s)] =
            __float2half(v);
    }
}

// ================= conv2: 64px strip x 32oc-half, warp tile 32px x 32oc =================
// slot layout: x-hi [0,8448), x-lo [8448,16896), U-hi [16896,19008), U-lo [19008,21120)
#define C2_WU 36864
#define C2_SLOT0 46080
#define C2_SLOTSZ 21120

__device__ __forceinline__ void c2_stage(u32 sb, int b, int x0, int ys, u32 slot, int tid) {
    bool yok = (unsigned)ys < 256u;
    int ysc = yok ? ys : 0;
    for (int i = tid; i < 1320; i += 256) {
        if (i < 1056) {
            int var = i >= 528;
            int j = i - var * 528;
            int px = j >> 3, c8 = j & 7;
            int gx = x0 - 1 + px;
            bool ok = yok && (unsigned)gx < 256u;
            int gxc = ((unsigned)gx < 256u) ? gx : 0;
            const void* src = &g_in[PLANE(var, 0, b) +
                                    (((size_t)(ysc * 256 + gxc)) << 6) + c8 * 8];
            u32 dst = sb + slot + (u32)(var * 8448 + px * 128) +
                      (u32)((c8 * 16) ^ ((px & 7) << 4));
            cpa16(dst, src, ok);
        } else {
            int j = i - 1056;
            int var = j >= 132;
            int jj = j - var * 132;
            int px = jj >> 1, hf = jj & 1;
            int gx = x0 - 1 + px;
            bool ok = yok && (unsigned)gx < 256u;
            int gxc = ((unsigned)gx < 256u) ? gx : 0;
            const __half* bp = var ? g_Ul : g_Uh;
            const void* src = &bp[((size_t)b * HWN + (size_t)(ysc * 256 + gxc)) * 16 + hf * 8];
            u32 dst = sb + slot + 16896 + (u32)(var * 2112 + px * 32 + hf * 16);
            cpa16(dst, src, ok);
        }
    }
}

__global__ __launch_bounds__(256, 1)
void conv2_kernel(const float* __restrict__ x, float* __restrict__ out) {
    extern __shared__ __align__(16) unsigned char sm[];
    u32 sb = smem_u32(sm);
    int tid = threadIdx.x, lane = tid & 31, wid = tid >> 5;
    int xs = blockIdx.x & 3, oh = blockIdx.x >> 2;
    int b = blockIdx.z, y0 = blockIdx.y * 32, x0 = xs * 64;

    // weights: x 36KB (this half) + U 9KB (this half, this batch)
    for (int i = tid; i < 36864 / 16; i += 256)
        ((uint4*)sm)[i] = ((const uint4*)(g_Wc2 + oh * 36864))[i];
    for (int i = tid; i < 9216 / 16; i += 256)
        ((uint4*)(sm + C2_WU))[i] =
            ((const uint4*)((const unsigned char*)g_W2 + (size_t)b * 18432 + oh * 9216))[i];

    int i8 = lane & 7, a_mh = (lane >> 3) & 1, a_kh = lane >> 4;
    int b_kh = (lane >> 3) & 1, b_nh = lane >> 4;
    int wm = wid & 1, ym = wid >> 1;                  // 2 warps/row, 4 rows/iter
    int apx = wm * 32 + a_mh * 8 + i8;
    u32 ocw[2];
    ocw[0] = (u32)(b_nh * 8 + i8);
    ocw[1] = ocw[0] + 16;
    int g = lane >> 2, t4 = lane & 3;

    // prologue: rows y0-1 .. y0+4 into slots (r+6)%6
    for (int r = -1; r <= 4; r++)
        c2_stage(sb, b, x0, y0 + r, C2_SLOT0 + (u32)((r + 6) % 6) * C2_SLOTSZ, tid);
    CP_COMMIT();
    CP_WAIT0();
    __syncthreads();

    for (int t = 0; t < 8; t++) {
        int y = 4 * t + ym;
        int yy = y0 + y;

        float acc[2][4][4];
#pragma unroll
        for (int m = 0; m < 2; m++)
#pragma unroll
            for (int j = 0; j < 4; j++)
#pragma unroll
                for (int q = 0; q < 4; q++) acc[m][j][q] = 0.f;

#pragma unroll
        for (int ky = 0; ky < 3; ky++) {
            u32 sl = sb + C2_SLOT0 + (u32)(((y + ky - 1 + 6) % 6)) * C2_SLOTSZ;
#pragma unroll
            for (int kx = 0; kx < 3; kx++) {
                int tap = ky * 3 + kx;
                int p = apx + kx;
                u32 aoff = (u32)(p * 128);
                u32 asw = (u32)((p & 7) << 4);
                // x part: 4 k16 chunks
#pragma unroll
                for (int kc = 0; kc < 4; kc++) {
                    u32 kb = ((u32)(kc * 32 + a_kh * 16)) ^ asw;
                    u32 Ah0[4], Ah1[4], Al0[4], Al1[4];
                    ldm4(Ah0, sl + aoff + kb);
                    ldm4(Ah1, sl + aoff + 2048 + kb);
                    ldm4(Al0, sl + 8448 + aoff + kb);
                    ldm4(Al1, sl + 8448 + aoff + 2048 + kb);
                    u32 BH0[4], BH1[4];
                    u32 bcol = (u32)(kc * 32 + b_kh * 16);
                    u32 b0 = sb + (u32)(tap * 4096) + ocw[0] * 128 +
                             (bcol ^ ((ocw[0] & 7) << 4));
                    u32 b1 = sb + (u32)(tap * 4096) + ocw[1] * 128 +
                             (bcol ^ ((ocw[1] & 7) << 4));
                    ldm4(BH0, b0);
                    ldm4(BH1, b1);
#pragma unroll
                    for (int j = 0; j < 2; j++) {
                        mma16816(acc[0][j],     Ah0, BH0 + 2 * j);
                        mma16816(acc[0][j],     Al0, BH0 + 2 * j);
                        mma16816(acc[0][2 + j], Ah0, BH1 + 2 * j);
                        mma16816(acc[0][2 + j], Al0, BH1 + 2 * j);
                        mma16816(acc[1][j],     Ah1, BH0 + 2 * j);
                        mma16816(acc[1][j],     Al1, BH0 + 2 * j);
                        mma16816(acc[1][2 + j], Ah1, BH1 + 2 * j);
                        mma16816(acc[1][2 + j], Al1, BH1 + 2 * j);
                    }
                }
                // U part: single k16 (16 subspace channels)
                {
                    u32 uoff = sl + 16896 + (u32)(p * 32 + a_kh * 16);
                    u32 Ah0[4], Ah1[4], Al0[4], Al1[4];
                    ldm4(Ah0, uoff);
                    ldm4(Ah1, uoff + 512);
                    ldm4(Al0, uoff + 2112);
                    ldm4(Al1, uoff + 2112 + 512);
                    u32 BH0[4], BH1[4];
                    u32 b0 = sb + C2_WU + (u32)(tap * 1024) + ocw[0] * 32 +
                             (u32)(b_kh * 16);
                    u32 b1 = sb + C2_WU + (u32)(tap * 1024) + ocw[1] * 32 +
                             (u32)(b_kh * 16);
                    ldm4(BH0, b0);
                    ldm4(BH1, b1);
#pragma unroll
                    for (int j = 0; j < 2; j++) {
                        mma16816(acc[0][j],     Ah0, BH0 + 2 * j);
                        mma16816(acc[0][j],     Al0, BH0 + 2 * j);
                        mma16816(acc[0][2 + j], Ah0, BH1 + 2 * j);
                        mma16816(acc[0][2 + j], Al0, BH1 + 2 * j);
                        mma16816(acc[1][j],     Ah1, BH0 + 2 * j);
                        mma16816(acc[1][j],     Al1, BH0 + 2 * j);
                        mma16816(acc[1][2 + j], Ah1, BH1 + 2 * j);
                        mma16816(acc[1][2 + j], Al1, BH1 + 2 * j);
                    }
                }
            }
        }
        // writeout + residual: 32px x 32oc per warp
        size_t rowb0 = (size_t)yy * 256;
#pragma unroll
        for (int m = 0; m < 2; m++) {
            int px = x0 + wm * 32 + m * 16 + g;
            size_t rowb = rowb0 + px;
#pragma unroll
            for (int j4 = 0; j4 < 4; j4++) {
                int oc = oh * 32 + (j4 >> 1) * 16 + (j4 & 1) * 8 + 2 * t4;
                size_t o0 = ((size_t)(b * 64 + oc) << 16) + rowb;
                size_t o1 = o0 + HWN;
                out[o0] = acc[m][j4][0] + x[o0];
                out[o1] = acc[m][j4][1] + x[o1];
                out[o0 + 8] = acc[m][j4][2] + x[o0 + 8];
                out[o1 + 8] = acc[m][j4][3] + x[o1 + 8];
            }
        }

        __syncthreads();
        if (t < 7) {
#pragma unroll
            for (int r = 5; r <= 8; r++)
                c2_stage(sb, b, x0, y0 + 4 * t + r,
                         C2_SLOT0 + (u32)((4 * t + r) % 6) * C2_SLOTSZ, tid);
            CP_COMMIT();
            CP_WAIT0();
            __syncthreads();
        }
    }
}

// ================= launch =================
extern "C" void kernel_launch(void* const* d_in, const int* in_sizes, int n_in,
                              void* d_out, int out_size) {
    const float* x      = (const float*)d_in[0];
    const float* bridge = (const float*)d_in[1];
    const float* Wsub   = (const float*)d_in[2];
    const float* Wcb    = (const float*)d_in[3];
    float* out = (float*)d_out;

    cudaFuncSetAttribute(conv1_kernel, cudaFuncAttributeMaxDynamicSharedMemorySize, 172032);
    cudaFuncSetAttribute(conv2_kernel, cudaFuncAttributeMaxDynamicSharedMemorySize, 172800);

    prep_w_kernel<<<288, 256>>>(Wsub, Wcb);
    convert_kernel<<<dim3(1024, 2, 8), 256>>>(x, bridge);
    conv1_kernel<<<dim3(4, 16, 8), 128, 172032>>>();
    reduce_kernel<<<dim3(NCHUNK, BB), 256>>>(bridge);
    solve_kernel<<<BB, 256>>>();
    w2eff_kernel<<<BB, 256>>>(Wcb);
    conv2_kernel<<<dim3(8, 8, 8), 256, 172800>>>(x, out);
}

// round 13
// speedup vs baseline: 2.0700x; 1.4521x over previous
#include <cuda_runtime.h>
#include <cuda_fp16.h>
#include <cstdint>

#define BB 8
#define HWN 65536
#define NCHUNK 128
#define PART_STRIDE 1296

typedef uint32_t u32;

// ================= device scratch =================
// NHWC fp16 planes (single precision level): [cg(0:x,1:bridge)][b][pixel][64ch]
__device__ __align__(16) __half g_in[(size_t)2 * 8 * HWN * 64];
#define PLANE(cg, b) (((size_t)((cg) * 8 + (b))) << 22)
__device__ __align__(16) float g_U[(size_t)BB * 16 * HWN];
__device__ __align__(16) __half g_Uh[(size_t)BB * HWN * 16];
__device__ __align__(16) float g_part[BB * NCHUNK * PART_STRIDE];
__device__ __align__(16) float g_PF2[BB * 16 * 64];
// conv1 weights fp16: [tap][16oc][128ic] = 36864 B
__device__ __align__(16) unsigned char g_Wc1[36864];
// conv2 x-weights fp16, ochalf-major: [oh][tap][32oc][64ic] = 73728 B
__device__ __align__(16) unsigned char g_Wc2[73728];
// conv2 U-weights fp16 per batch: [b][oh][tap][32oc][16s]
__device__ __align__(16) __half g_W2[(size_t)BB * 9216];

// ================= helpers =================
__device__ __forceinline__ u32 smem_u32(const void* p) {
    u32 a;
    asm("{ .reg .u64 t; cvta.to.shared.u64 t, %1; cvt.u32.u64 %0, t; }" : "=r"(a) : "l"(p));
    return a;
}
__device__ __forceinline__ void ldm4(u32* r, u32 a) {
    asm volatile("ldmatrix.sync.aligned.m8n8.x4.shared.b16 {%0,%1,%2,%3}, [%4];"
                 : "=r"(r[0]), "=r"(r[1]), "=r"(r[2]), "=r"(r[3]) : "r"(a));
}
__device__ __forceinline__ void mma16816(float* c, const u32* a, const u32* b) {
    asm volatile("mma.sync.aligned.m16n8k16.row.col.f32.f16.f16.f32 "
                 "{%0,%1,%2,%3}, {%4,%5,%6,%7}, {%8,%9}, {%0,%1,%2,%3};"
                 : "+f"(c[0]), "+f"(c[1]), "+f"(c[2]), "+f"(c[3])
                 : "r"(a[0]), "r"(a[1]), "r"(a[2]), "r"(a[3]), "r"(b[0]), "r"(b[1]));
}
__device__ __forceinline__ void cpa16(u32 dst, const void* src, bool pred) {
    unsigned sz = pred ? 16u : 0u;
    asm volatile("cp.async.cg.shared.global [%0], [%1], 16, %2;"
                 :: "r"(dst), "l"(__cvta_generic_to_global(src)), "r"(sz));
}
#define CP_COMMIT() asm volatile("cp.async.commit_group;" ::: "memory")
#define CP_WAIT0()  asm volatile("cp.async.wait_group 0;" ::: "memory")

// ================= weight prep (single fp16) =================
__global__ void prep_w_kernel(const float* __restrict__ Ws, const float* __restrict__ Wc) {
    int id = blockIdx.x * 256 + threadIdx.x;
    if (id < 64 * 1152) {
        int oc = id / 1152, rem = id - oc * 1152, ic = rem / 9, tap = rem - ic * 9;
        if (ic < 64) {
            int oh = oc >> 5, ocl = oc & 31;
            u32 off = (u32)(oh * 36864 + tap * 4096 + ocl * 128) +
                      (u32)((ic * 2) ^ ((ocl & 7) << 4));
            *(__half*)(g_Wc2 + off) = __float2half(Wc[id]);
        }
    }
    if (id < 16 * 1152) {
        int oc = id / 1152, rem = id - oc * 1152, ic = rem / 9, tap = rem - ic * 9;
        u32 off = (u32)((tap * 16 + oc) * 256) + (u32)((ic * 2) ^ ((oc & 7) << 4));
        *(__half*)(g_Wc1 + off) = __float2half(Ws[id]);
    }
}

// ================= NCHW fp32 -> NHWC fp16 =================
__global__ __launch_bounds__(256)
void convert_kernel(const float* __restrict__ x, const float* __restrict__ bridge) {
    __shared__ float sT[64][68];
    int b = blockIdx.z, cg = blockIdx.y, pb = blockIdx.x;
    const float* src = cg ? bridge : x;
    int tid = threadIdx.x;
    int p0 = pb * 64;
    for (int i = tid; i < 64 * 64; i += 256) {
        int c = i >> 6, px = i & 63;
        sT[c][px] = src[((size_t)(b * 64 + c) << 16) + p0 + px];
    }
    __syncthreads();
    for (int i = tid; i < 512; i += 256) {
        int px = i >> 3, c8 = i & 7;
        __half hb[8];
#pragma unroll
        for (int j = 0; j < 8; j++)
            hb[j] = __float2half(sT[c8 * 8 + j][px]);
        size_t base = ((size_t)(p0 + px) << 6) + c8 * 8;
        *(uint4*)&g_in[PLANE(cg, b) + base] = *(uint4*)hb;
    }
}

// ================= conv1: 64px strip, 4 warps, warp tile 16px x 16oc x 2 rows =================
// slot planes: x [0,8448), bridge [8448,16896)
#define C1_SLOT0 36864
#define C1_SLOTSZ 16896

__device__ __forceinline__ void c1_stage(u32 sb, int b, int x0, int ys, u32 slot, int tid) {
    bool yok = (unsigned)ys < 256u;
    int ysc = yok ? ys : 0;
    for (int i = tid; i < 1056; i += 128) {
        int p = i / 528, j = i - p * 528;          // p = cg
        int px = j >> 3, c8 = j & 7;
        int gx = x0 - 1 + px;
        bool ok = yok && (unsigned)gx < 256u;
        int gxc = ((unsigned)gx < 256u) ? gx : 0;
        const void* src = &g_in[PLANE(p, b) +
                                (((size_t)(ysc * 256 + gxc)) << 6) + c8 * 8];
        u32 dst = sb + slot + (u32)(p * 8448 + px * 128) +
                  (u32)((c8 * 16) ^ ((px & 7) << 4));
        cpa16(dst, src, ok);
    }
}

__global__ __launch_bounds__(128)
void conv1_kernel() {
    extern __shared__ __align__(16) unsigned char sm[];
    u32 sb = smem_u32(sm);
    int tid = threadIdx.x, lane = tid & 31, wid = tid >> 5;
    int b = blockIdx.z, y0 = blockIdx.y * 16, x0 = blockIdx.x * 64;

    for (int i = tid; i < 36864 / 16; i += 128)
        ((uint4*)sm)[i] = ((const uint4*)g_Wc1)[i];

    int i8 = lane & 7, a_mh = (lane >> 3) & 1, a_kh = lane >> 4;
    int b_kh = (lane >> 3) & 1, b_nh = lane >> 4;
    int wm = wid;                              // 4 m-warps x 16px
    int apx = wm * 16 + a_mh * 8 + i8;
    int ocw = b_nh * 8 + i8;                   // 16 oc rows
    u32 bRow = (u32)(ocw * 256), bx = (u32)((ocw & 7) << 4);
    int g = lane >> 2, t4 = lane & 3;

    // prologue: rows y0-1 .. y0+2 into slots 3,0,1,2
    c1_stage(sb, b, x0, y0 - 1, C1_SLOT0 + 3u * C1_SLOTSZ, tid);
    c1_stage(sb, b, x0, y0 + 0, C1_SLOT0 + 0u * C1_SLOTSZ, tid);
    c1_stage(sb, b, x0, y0 + 1, C1_SLOT0 + 1u * C1_SLOTSZ, tid);
    c1_stage(sb, b, x0, y0 + 2, C1_SLOT0 + 2u * C1_SLOTSZ, tid);
    CP_COMMIT();
    CP_WAIT0();
    __syncthreads();

    for (int t = 0; t < 8; t++) {
        float acc[2][2][4];
#pragma unroll
        for (int r = 0; r < 2; r++)
#pragma unroll
            for (int j = 0; j < 2; j++)
#pragma unroll
                for (int q = 0; q < 4; q++) acc[r][j][q] = 0.f;

#pragma unroll
        for (int ky = 0; ky < 3; ky++) {
            u32 sl0 = sb + C1_SLOT0 + (u32)(((2 * t + ky - 1) & 3)) * C1_SLOTSZ; // row 2t
            u32 sl1 = sb + C1_SLOT0 + (u32)(((2 * t + ky) & 3)) * C1_SLOTSZ;     // row 2t+1
#pragma unroll
            for (int kx = 0; kx < 3; kx++) {
                int tap = ky * 3 + kx;
                int p = apx + kx;
                u32 aoff = (u32)(p * 128);
                u32 asw = (u32)((p & 7) << 4);
#pragma unroll
                for (int cg = 0; cg < 2; cg++) {
#pragma unroll
                    for (int kc = 0; kc < 4; kc++) {
                        u32 kb = ((u32)(kc * 32 + a_kh * 16)) ^ asw;
                        u32 Ah0[4], Ah1[4];
                        ldm4(Ah0, sl0 + (u32)(cg * 8448) + aoff + kb);
                        ldm4(Ah1, sl1 + (u32)(cg * 8448) + aoff + kb);
                        u32 ba = sb + (u32)(tap * 4096) + bRow +
                                 (((u32)(cg * 128 + kc * 32 + b_kh * 16)) ^ bx);
                        u32 BH[4];
                        ldm4(BH, ba);
#pragma unroll
                        for (int j = 0; j < 2; j++) {
                            mma16816(acc[0][j], Ah0, BH + 2 * j);
                            mma16816(acc[1][j], Ah1, BH + 2 * j);
                        }
                    }
                }
            }
        }
        // writeout rows 2t, 2t+1: fp32 U + fp16 U
#pragma unroll
        for (int r = 0; r < 2; r++) {
            int yy = y0 + 2 * t + r;
            int px = x0 + wm * 16 + g;
            size_t rowb = (size_t)yy * 256 + px;
#pragma unroll
            for (int j = 0; j < 2; j++) {
                int oc = j * 8 + 2 * t4;
                g_U[((size_t)(b * 16 + oc) << 16) + rowb] = acc[r][j][0];
                g_U[((size_t)(b * 16 + oc + 1) << 16) + rowb] = acc[r][j][1];
                g_U[((size_t)(b * 16 + oc) << 16) + rowb + 8] = acc[r][j][2];
                g_U[((size_t)(b * 16 + oc + 1) << 16) + rowb + 8] = acc[r][j][3];
                size_t idx = ((size_t)b * HWN + rowb) * 16 + oc;
                __half2 hh;
                hh.x = __float2half(acc[r][j][0]);
                hh.y = __float2half(acc[r][j][1]);
                *(__half2*)&g_Uh[idx] = hh;
                hh.x = __float2half(acc[r][j][2]);
                hh.y = __float2half(acc[r][j][3]);
                *(__half2*)&g_Uh[idx + 128] = hh;
            }
        }

        __syncthreads();
        if (t < 7) {
            c1_stage(sb, b, x0, y0 + 2 * t + 3,
                     C1_SLOT0 + (u32)((2 * t + 3) & 3) * C1_SLOTSZ, tid);
            c1_stage(sb, b, x0, y0 + 2 * t + 4,
                     C1_SLOT0 + (u32)((2 * t + 4) & 3) * C1_SLOTSZ, tid);
            CP_COMMIT();
            CP_WAIT0();
            __syncthreads();
        }
    }
}

// ================= reduction (fp32, unchanged) =================
__global__ __launch_bounds__(256)
void reduce_kernel(const float* __restrict__ bridge) {
    __shared__ __align__(16) float sU[16][68];
    __shared__ __align__(16) float sB[64][68];
    int b = blockIdx.y, ch = blockIdx.x;
    int tid = threadIdx.x;
    int s = tid >> 4, q = tid & 15;
    int n0 = ch * 512;
    const float* Ub = g_U + (size_t)b * 16 * HWN;
    const float* Bb = bridge + (size_t)b * 64 * HWN;
    float accG[4] = {0.f, 0.f, 0.f, 0.f};
    float accM = 0.f, accR = 0.f;
    for (int sub = 0; sub < 8; sub++) {
        int n = n0 + sub * 64;
        {
            int sl = tid >> 4, p4 = (tid & 15) * 4;
            *reinterpret_cast<float4*>(&sU[sl][p4]) =
                *reinterpret_cast<const float4*>(&Ub[sl * HWN + n + p4]);
        }
#pragma unroll
        for (int r = 0; r < 4; r++) {
            int cl = (tid >> 4) + r * 16;
            int p4 = (tid & 15) * 4;
            *reinterpret_cast<float4*>(&sB[cl][p4]) =
                *reinterpret_cast<const float4*>(&Bb[cl * HWN + n + p4]);
        }
        __syncthreads();
#pragma unroll
        for (int p = 0; p < 64; p += 4) {
            float4 u = *reinterpret_cast<float4*>(&sU[s][p]);
            float4 t4 = *reinterpret_cast<float4*>(&sU[q][p]);
            accM += u.x * t4.x + u.y * t4.y + u.z * t4.z + u.w * t4.w;
#pragma unroll
            for (int j = 0; j < 4; j++) {
                float4 bv = *reinterpret_cast<float4*>(&sB[q + j * 16][p]);
                accG[j] += u.x * bv.x + u.y * bv.y + u.z * bv.z + u.w * bv.w;
            }
            if (q == 0) accR += fabsf(u.x) + fabsf(u.y) + fabsf(u.z) + fabsf(u.w);
        }
        __syncthreads();
    }
    float* o = g_part + (size_t)(b * NCHUNK + ch) * PART_STRIDE;
    o[s * 16 + q] = accM;
#pragma unroll
    for (int j = 0; j < 4; j++) o[256 + s * 64 + q + j * 16] = accG[j];
    if (q == 0) o[1280 + s] = accR;
}

// ================= solve (unchanged) =================
__global__ __launch_bounds__(256)
void solve_kernel() {
    __shared__ float sGram[256];
    __shared__ float sG[1024];
    __shared__ float srr[16];
    __shared__ double A[16][17];
    __shared__ double M[16][17];
    __shared__ double spiv;
    int b = blockIdx.x;
    int tid = threadIdx.x;
    const float* base = g_part + (size_t)b * NCHUNK * PART_STRIDE;
    {
        float a = 0.f;
        for (int ch = 0; ch < NCHUNK; ch++) a += base[ch * PART_STRIDE + tid];
        sGram[tid] = a;
    }
#pragma unroll
    for (int j = 0; j < 4; j++) {
        int e = tid + j * 256;
        float a = 0.f;
        for (int ch = 0; ch < NCHUNK; ch++) a += base[ch * PART_STRIDE + 256 + e];
        sG[e] = a;
    }
    if (tid < 16) {
        float a = 0.f;
        for (int ch = 0; ch < NCHUNK; ch++) a += base[ch * PART_STRIDE + 1280 + tid];
        srr[tid] = 1e-6f + a;
    }
    __syncthreads();
    {
        int i = tid >> 4, t = tid & 15;
        A[i][t] = (double)sGram[tid] / ((double)srr[i] * (double)srr[t]);
        M[i][t] = (i == t) ? 1.0 : 0.0;
    }
    __syncthreads();
    for (int k = 0; k < 16; k++) {
        if (tid == 0) spiv = 1.0 / A[k][k];
        __syncthreads();
        if (tid < 16) { A[k][tid] *= spiv; M[k][tid] *= spiv; }
        __syncthreads();
        int i = tid >> 4, t = tid & 15;
        double f = A[i][k];
        __syncthreads();
        if (i != k) { A[i][t] -= f * A[k][t]; M[i][t] -= f * M[k][t]; }
        __syncthreads();
    }
#pragma unroll
    for (int j = 0; j < 4; j++) {
        int e = tid + j * 256;
        int s = e >> 6, c = e & 63;
        double v = 0.0;
#pragma unroll
        for (int t = 0; t < 16; t++)
            v += M[s][t] * ((double)sG[t * 64 + c] / (double)srr[t]);
        g_PF2[b * 1024 + e] = (float)(v / (double)srr[s]);
    }
}

// ================= fold PF2 into conv2 proj-weights (fp16, ochalf-major) =================
__global__ __launch_bounds__(256)
void w2eff_kernel(const float* __restrict__ Wc) {
    __shared__ float sPF[1024];
    int b = blockIdx.x, tid = threadIdx.x;
    for (int i = tid; i < 1024; i += 256) sPF[i] = g_PF2[b * 1024 + i];
    __syncthreads();
    for (int e = tid; e < 9216; e += 256) {
        int tap = e / 1024, r = e & 1023, o = r >> 4, s = r & 15;
        float v = 0.f;
#pragma unroll
        for (int c = 0; c < 64; c++)
            v += Wc[o * 1152 + (64 + c) * 9 + tap] * sPF[s * 64 + c];
        int oh = o >> 5, ocl = o & 31;
        g_W2[(size_t)b * 9216 + (size_t)(oh * 4608 + tap * 512 + ocl * 16 + s)] =
            __float2half(v);
    }
}

// ================= conv2: 64px strip x 32oc-half, warp tile 32px x 32oc =================
// slot layout: x [0,8448), U [8448,10560)
#define C2_WU 36864
#define C2_SLOT0 46080
#define C2_SLOTSZ 10560

__device__ __forceinline__ void c2_stage(u32 sb, int b, int x0, int ys, u32 slot, int tid) {
    bool yok = (unsigned)ys < 256u;
    int ysc = yok ? ys : 0;
    for (int i = tid; i < 660; i += 256) {
        if (i < 528) {
            int px = i >> 3, c8 = i & 7;
            int gx = x0 - 1 + px;
            bool ok = yok && (unsigned)gx < 256u;
            int gxc = ((unsigned)gx < 256u) ? gx : 0;
            const void* src = &g_in[PLANE(0, b) +
                                    (((size_t)(ysc * 256 + gxc)) << 6) + c8 * 8];
            u32 dst = sb + slot + (u32)(px * 128) +
                      (u32)((c8 * 16) ^ ((px & 7) << 4));
            cpa16(dst, src, ok);
        } else {
            int j = i - 528;
            int px = j >> 1, hf = j & 1;
            int gx = x0 - 1 + px;
            bool ok = yok && (unsigned)gx < 256u;
            int gxc = ((unsigned)gx < 256u) ? gx : 0;
            const void* src = &g_Uh[((size_t)b * HWN + (size_t)(ysc * 256 + gxc)) * 16 +
                                    hf * 8];
            u32 dst = sb + slot + 8448 + (u32)(px * 32 + hf * 16);
            cpa16(dst, src, ok);
        }
    }
}

__global__ __launch_bounds__(256)
void conv2_kernel(const float* __restrict__ x, float* __restrict__ out) {
    extern __shared__ __align__(16) unsigned char sm[];
    u32 sb = smem_u32(sm);
    int tid = threadIdx.x, lane = tid & 31, wid = tid >> 5;
    int xs = blockIdx.x & 3, oh = blockIdx.x >> 2;
    int b = blockIdx.z, y0 = blockIdx.y * 32, x0 = xs * 64;

    // weights: x 36KB (this half) + U 9KB (this half, this batch)
    for (int i = tid; i < 36864 / 16; i += 256)
        ((uint4*)sm)[i] = ((const uint4*)(g_Wc2 + oh * 36864))[i];
    for (int i = tid; i < 9216 / 16; i += 256)
        ((uint4*)(sm + C2_WU))[i] =
            ((const uint4*)((const unsigned char*)g_W2 + (size_t)b * 18432 + oh * 9216))[i];

    int i8 = lane & 7, a_mh = (lane >> 3) & 1, a_kh = lane >> 4;
    int b_kh = (lane >> 3) & 1, b_nh = lane >> 4;
    int wm = wid & 1, ym = wid >> 1;                  // 2 warps/row, 4 rows/iter
    int apx = wm * 32 + a_mh * 8 + i8;
    u32 ocw[2];
    ocw[0] = (u32)(b_nh * 8 + i8);
    ocw[1] = ocw[0] + 16;
    int g = lane >> 2, t4 = lane & 3;

    // prologue: rows y0-1 .. y0+4 into slots (r+6)%6
    for (int r = -1; r <= 4; r++)
        c2_stage(sb, b, x0, y0 + r, C2_SLOT0 + (u32)((r + 6) % 6) * C2_SLOTSZ, tid);
    CP_COMMIT();
    CP_WAIT0();
    __syncthreads();

    for (int t = 0; t < 8; t++) {
        int y = 4 * t + ym;
        int yy = y0 + y;

        float acc[2][4][4];
#pragma unroll
        for (int m = 0; m < 2; m++)
#pragma unroll
            for (int j = 0; j < 4; j++)
#pragma unroll
                for (int q = 0; q < 4; q++) acc[m][j][q] = 0.f;

#pragma unroll
        for (int ky = 0; ky < 3; ky++) {
            u32 sl = sb + C2_SLOT0 + (u32)(((y + ky - 1 + 6) % 6)) * C2_SLOTSZ;
#pragma unroll
            for (int kx = 0; kx < 3; kx++) {
                int tap = ky * 3 + kx;
                int p = apx + kx;
                u32 aoff = (u32)(p * 128);
                u32 asw = (u32)((p & 7) << 4);
                // x part: 4 k16 chunks
#pragma unroll
                for (int kc = 0; kc < 4; kc++) {
                    u32 kb = ((u32)(kc * 32 + a_kh * 16)) ^ asw;
                    u32 Ah0[4], Ah1[4];
                    ldm4(Ah0, sl + aoff + kb);
                    ldm4(Ah1, sl + aoff + 2048 + kb);
                    u32 BH0[4], BH1[4];
                    u32 bcol = (u32)(kc * 32 + b_kh * 16);
                    u32 b0 = sb + (u32)(tap * 4096) + ocw[0] * 128 +
                             (bcol ^ ((ocw[0] & 7) << 4));
                    u32 b1 = sb + (u32)(tap * 4096) + ocw[1] * 128 +
                             (bcol ^ ((ocw[1] & 7) << 4));
                    ldm4(BH0, b0);
                    ldm4(BH1, b1);
#pragma unroll
                    for (int j = 0; j < 2; j++) {
                        mma16816(acc[0][j],     Ah0, BH0 + 2 * j);
                        mma16816(acc[0][2 + j], Ah0, BH1 + 2 * j);
                        mma16816(acc[1][j],     Ah1, BH0 + 2 * j);
                        mma16816(acc[1][2 + j], Ah1, BH1 + 2 * j);
                    }
                }
                // U part: single k16 (16 subspace channels)
                {
                    u32 uoff = sl + 8448 + (u32)(p * 32 + a_kh * 16);
                    u32 Ah0[4], Ah1[4];
                    ldm4(Ah0, uoff);
                    ldm4(Ah1, uoff + 512);
                    u32 BH0[4], BH1[4];
                    u32 b0 = sb + C2_WU + (u32)(tap * 1024) + ocw[0] * 32 +
                             (u32)(b_kh * 16);
                    u32 b1 = sb + C2_WU + (u32)(tap * 1024) + ocw[1] * 32 +
                             (u32)(b_kh * 16);
                    ldm4(BH0, b0);
                    ldm4(BH1, b1);
#pragma unroll
                    for (int j = 0; j < 2; j++) {
                        mma16816(acc[0][j],     Ah0, BH0 + 2 * j);
                        mma16816(acc[0][2 + j], Ah0, BH1 + 2 * j);
                        mma16816(acc[1][j],     Ah1, BH0 + 2 * j);
                        mma16816(acc[1][2 + j], Ah1, BH1 + 2 * j);
                    }
                }
            }
        }
        // writeout + residual: 32px x 32oc per warp
        size_t rowb0 = (size_t)yy * 256;
#pragma unroll
        for (int m = 0; m < 2; m++) {
            int px = x0 + wm * 32 + m * 16 + g;
            size_t rowb = rowb0 + px;
#pragma unroll
            for (int j4 = 0; j4 < 4; j4++) {
                int oc = oh * 32 + (j4 >> 1) * 16 + (j4 & 1) * 8 + 2 * t4;
                size_t o0 = ((size_t)(b * 64 + oc) << 16) + rowb;
                size_t o1 = o0 + HWN;
                out[o0] = acc[m][j4][0] + x[o0];
                out[o1] = acc[m][j4][1] + x[o1];
                out[o0 + 8] = acc[m][j4][2] + x[o0 + 8];
                out[o1 + 8] = acc[m][j4][3] + x[o1 + 8];
            }
        }

        __syncthreads();
        if (t < 7) {
#pragma unroll
            for (int r = 5; r <= 8; r++)
                c2_stage(sb, b, x0, y0 + 4 * t + r,
                         C2_SLOT0 + (u32)((4 * t + r) % 6) * C2_SLOTSZ, tid);
            CP_COMMIT();
            CP_WAIT0();
            __syncthreads();
        }
    }
}

// ================= launch =================
extern "C" void kernel_launch(void* const* d_in, const int* in_sizes, int n_in,
                              void* d_out, int out_size) {
    const float* x      = (const float*)d_in[0];
    const float* bridge = (const float*)d_in[1];
    const float* Wsub   = (const float*)d_in[2];
    const float* Wcb    = (const float*)d_in[3];
    float* out = (float*)d_out;

    cudaFuncSetAttribute(conv1_kernel, cudaFuncAttributeMaxDynamicSharedMemorySize, 104448);
    cudaFuncSetAttribute(conv2_kernel, cudaFuncAttributeMaxDynamicSharedMemorySize, 109440);

    prep_w_kernel<<<288, 256>>>(Wsub, Wcb);
    convert_kernel<<<dim3(1024, 2, 8), 256>>>(x, bridge);
    conv1_kernel<<<dim3(4, 16, 8), 128, 104448>>>();
    reduce_kernel<<<dim3(NCHUNK, BB), 256>>>(bridge);
    solve_kernel<<<BB, 256>>>();
    w2eff_kernel<<<BB, 256>>>(Wcb);
    conv2_kernel<<<dim3(8, 8, 8), 256, 109440>>>(x, out);
}

// round 14
// speedup vs baseline: 2.3805x; 1.1500x over previous
#include <cuda_runtime.h>
#include <cuda_fp16.h>
#include <cstdint>

#define BB 8
#define HWN 65536
#define NCHUNK 128
#define PART_STRIDE 1296

typedef uint32_t u32;

// ================= device scratch =================
// NHWC fp16 planes: [cg(0:x,1:bridge)][b][pixel][64ch]
__device__ __align__(16) __half g_in[(size_t)2 * 8 * HWN * 64];
#define PLANE(cg, b) (((size_t)((cg) * 8 + (b))) << 22)
__device__ __align__(16) __half g_Uh[(size_t)BB * HWN * 16];
__device__ __align__(16) float g_part[BB * NCHUNK * PART_STRIDE];
__device__ __align__(16) float g_PF2[BB * 16 * 64];
__device__ __align__(16) unsigned char g_Wc1[36864];
__device__ __align__(16) unsigned char g_Wc2[73728];
__device__ __align__(16) __half g_W2[(size_t)BB * 9216];

// ================= helpers =================
__device__ __forceinline__ u32 smem_u32(const void* p) {
    u32 a;
    asm("{ .reg .u64 t; cvta.to.shared.u64 t, %1; cvt.u32.u64 %0, t; }" : "=r"(a) : "l"(p));
    return a;
}
__device__ __forceinline__ void ldm4(u32* r, u32 a) {
    asm volatile("ldmatrix.sync.aligned.m8n8.x4.shared.b16 {%0,%1,%2,%3}, [%4];"
                 : "=r"(r[0]), "=r"(r[1]), "=r"(r[2]), "=r"(r[3]) : "r"(a));
}
__device__ __forceinline__ void ldm4t(u32* r, u32 a) {
    asm volatile("ldmatrix.sync.aligned.m8n8.x4.trans.shared.b16 {%0,%1,%2,%3}, [%4];"
                 : "=r"(r[0]), "=r"(r[1]), "=r"(r[2]), "=r"(r[3]) : "r"(a));
}
__device__ __forceinline__ void mma16816(float* c, const u32* a, const u32* b) {
    asm volatile("mma.sync.aligned.m16n8k16.row.col.f32.f16.f16.f32 "
                 "{%0,%1,%2,%3}, {%4,%5,%6,%7}, {%8,%9}, {%0,%1,%2,%3};"
                 : "+f"(c[0]), "+f"(c[1]), "+f"(c[2]), "+f"(c[3])
                 : "r"(a[0]), "r"(a[1]), "r"(a[2]), "r"(a[3]), "r"(b[0]), "r"(b[1]));
}
__device__ __forceinline__ void cpa16(u32 dst, const void* src, bool pred) {
    unsigned sz = pred ? 16u : 0u;
    asm volatile("cp.async.cg.shared.global [%0], [%1], 16, %2;"
                 :: "r"(dst), "l"(__cvta_generic_to_global(src)), "r"(sz));
}
#define CP_COMMIT() asm volatile("cp.async.commit_group;" ::: "memory")
#define CP_WAIT0()  asm volatile("cp.async.wait_group 0;" ::: "memory")

// ================= weight prep (single fp16) =================
__global__ void prep_w_kernel(const float* __restrict__ Ws, const float* __restrict__ Wc) {
    int id = blockIdx.x * 256 + threadIdx.x;
    if (id < 64 * 1152) {
        int oc = id / 1152, rem = id - oc * 1152, ic = rem / 9, tap = rem - ic * 9;
        if (ic < 64) {
            int oh = oc >> 5, ocl = oc & 31;
            u32 off = (u32)(oh * 36864 + tap * 4096 + ocl * 128) +
                      (u32)((ic * 2) ^ ((ocl & 7) << 4));
            *(__half*)(g_Wc2 + off) = __float2half(Wc[id]);
        }
    }
    if (id < 16 * 1152) {
        int oc = id / 1152, rem = id - oc * 1152, ic = rem / 9, tap = rem - ic * 9;
        u32 off = (u32)((tap * 16 + oc) * 256) + (u32)((ic * 2) ^ ((oc & 7) << 4));
        *(__half*)(g_Wc1 + off) = __float2half(Ws[id]);
    }
}

// ================= NCHW fp32 -> NHWC fp16 =================
__global__ __launch_bounds__(256)
void convert_kernel(const float* __restrict__ x, const float* __restrict__ bridge) {
    __shared__ float sT[64][68];
    int b = blockIdx.z, cg = blockIdx.y, pb = blockIdx.x;
    const float* src = cg ? bridge : x;
    int tid = threadIdx.x;
    int p0 = pb * 64;
    for (int i = tid; i < 64 * 64; i += 256) {
        int c = i >> 6, px = i & 63;
        sT[c][px] = src[((size_t)(b * 64 + c) << 16) + p0 + px];
    }
    __syncthreads();
    for (int i = tid; i < 512; i += 256) {
        int px = i >> 3, c8 = i & 7;
        __half hb[8];
#pragma unroll
        for (int j = 0; j < 8; j++)
            hb[j] = __float2half(sT[c8 * 8 + j][px]);
        size_t base = ((size_t)(p0 + px) << 6) + c8 * 8;
        *(uint4*)&g_in[PLANE(cg, b) + base] = *(uint4*)hb;
    }
}

// ================= conv1 =================
#define C1_SLOT0 36864
#define C1_SLOTSZ 16896

__device__ __forceinline__ void c1_stage(u32 sb, int b, int x0, int ys, u32 slot, int tid) {
    bool yok = (unsigned)ys < 256u;
    int ysc = yok ? ys : 0;
    for (int i = tid; i < 1056; i += 128) {
        int p = i / 528, j = i - p * 528;
        int px = j >> 3, c8 = j & 7;
        int gx = x0 - 1 + px;
        bool ok = yok && (unsigned)gx < 256u;
        int gxc = ((unsigned)gx < 256u) ? gx : 0;
        const void* src = &g_in[PLANE(p, b) +
                                (((size_t)(ysc * 256 + gxc)) << 6) + c8 * 8];
        u32 dst = sb + slot + (u32)(p * 8448 + px * 128) +
                  (u32)((c8 * 16) ^ ((px & 7) << 4));
        cpa16(dst, src, ok);
    }
}

__global__ __launch_bounds__(128)
void conv1_kernel() {
    extern __shared__ __align__(16) unsigned char sm[];
    u32 sb = smem_u32(sm);
    int tid = threadIdx.x, lane = tid & 31, wid = tid >> 5;
    int b = blockIdx.z, y0 = blockIdx.y * 16, x0 = blockIdx.x * 64;

    for (int i = tid; i < 36864 / 16; i += 128)
        ((uint4*)sm)[i] = ((const uint4*)g_Wc1)[i];

    int i8 = lane & 7, a_mh = (lane >> 3) & 1, a_kh = lane >> 4;
    int b_kh = (lane >> 3) & 1, b_nh = lane >> 4;
    int wm = wid;
    int apx = wm * 16 + a_mh * 8 + i8;
    int ocw = b_nh * 8 + i8;
    u32 bRow = (u32)(ocw * 256), bx = (u32)((ocw & 7) << 4);
    int g = lane >> 2, t4 = lane & 3;

    c1_stage(sb, b, x0, y0 - 1, C1_SLOT0 + 3u * C1_SLOTSZ, tid);
    c1_stage(sb, b, x0, y0 + 0, C1_SLOT0 + 0u * C1_SLOTSZ, tid);
    c1_stage(sb, b, x0, y0 + 1, C1_SLOT0 + 1u * C1_SLOTSZ, tid);
    c1_stage(sb, b, x0, y0 + 2, C1_SLOT0 + 2u * C1_SLOTSZ, tid);
    CP_COMMIT();
    CP_WAIT0();
    __syncthreads();

    for (int t = 0; t < 8; t++) {
        float acc[2][2][4];
#pragma unroll
        for (int r = 0; r < 2; r++)
#pragma unroll
            for (int j = 0; j < 2; j++)
#pragma unroll
                for (int q = 0; q < 4; q++) acc[r][j][q] = 0.f;

#pragma unroll
        for (int ky = 0; ky < 3; ky++) {
            u32 sl0 = sb + C1_SLOT0 + (u32)(((2 * t + ky - 1) & 3)) * C1_SLOTSZ;
            u32 sl1 = sb + C1_SLOT0 + (u32)(((2 * t + ky) & 3)) * C1_SLOTSZ;
#pragma unroll
            for (int kx = 0; kx < 3; kx++) {
                int tap = ky * 3 + kx;
                int p = apx + kx;
                u32 aoff = (u32)(p * 128);
                u32 asw = (u32)((p & 7) << 4);
#pragma unroll
                for (int cg = 0; cg < 2; cg++) {
#pragma unroll
                    for (int kc = 0; kc < 4; kc++) {
                        u32 kb = ((u32)(kc * 32 + a_kh * 16)) ^ asw;
                        u32 Ah0[4], Ah1[4];
                        ldm4(Ah0, sl0 + (u32)(cg * 8448) + aoff + kb);
                        ldm4(Ah1, sl1 + (u32)(cg * 8448) + aoff + kb);
                        u32 ba = sb + (u32)(tap * 4096) + bRow +
                                 (((u32)(cg * 128 + kc * 32 + b_kh * 16)) ^ bx);
                        u32 BH[4];
                        ldm4(BH, ba);
#pragma unroll
                        for (int j = 0; j < 2; j++) {
                            mma16816(acc[0][j], Ah0, BH + 2 * j);
                            mma16816(acc[1][j], Ah1, BH + 2 * j);
                        }
                    }
                }
            }
        }
#pragma unroll
        for (int r = 0; r < 2; r++) {
            int yy = y0 + 2 * t + r;
            int px = x0 + wm * 16 + g;
            size_t rowb = (size_t)yy * 256 + px;
#pragma unroll
            for (int j = 0; j < 2; j++) {
                int oc = j * 8 + 2 * t4;
                size_t idx = ((size_t)b * HWN + rowb) * 16 + oc;
                __half2 hh;
                hh.x = __float2half(acc[r][j][0]);
                hh.y = __float2half(acc[r][j][1]);
                *(__half2*)&g_Uh[idx] = hh;
                hh.x = __float2half(acc[r][j][2]);
                hh.y = __float2half(acc[r][j][3]);
                *(__half2*)&g_Uh[idx + 128] = hh;
            }
        }

        __syncthreads();
        if (t < 7) {
            c1_stage(sb, b, x0, y0 + 2 * t + 3,
                     C1_SLOT0 + (u32)((2 * t + 3) & 3) * C1_SLOTSZ, tid);
            c1_stage(sb, b, x0, y0 + 2 * t + 4,
                     C1_SLOT0 + (u32)((2 * t + 4) & 3) * C1_SLOTSZ, tid);
            CP_COMMIT();
            CP_WAIT0();
            __syncthreads();
        }
    }
}

// ================= reduction via mma: Gram[16,16], G[16,64], r[16] =================
// smem: U [0,24576): 512px x 48B pitch (32B used); B [24576,90112): 512px x 128B swizzled
// after compute: partials [0,40960) 8 warps x 1280 fp32; r_part [40960,41984)
#define RED_SM 90112

__global__ __launch_bounds__(256)
void reduce_kernel() {
    extern __shared__ __align__(16) unsigned char rsm[];
    u32 sb = smem_u32(rsm);
    int b = blockIdx.y, ch = blockIdx.x;
    int tid = threadIdx.x, lane = tid & 31, w = tid >> 5;
    int n0 = ch * 512;

    for (int i = tid; i < 1024; i += 256) {
        int px = i >> 1, hf = i & 1;
        cpa16(sb + (u32)(px * 48 + hf * 16),
              &g_Uh[((size_t)b * HWN + n0 + px) * 16 + hf * 8], true);
    }
    for (int i = tid; i < 4096; i += 256) {
        int px = i >> 3, c8 = i & 7;
        cpa16(sb + 24576 + (u32)(px * 128) + (u32)((c8 * 16) ^ ((px & 7) << 4)),
              &g_in[PLANE(1, b) + (((size_t)(n0 + px)) << 6) + c8 * 8], true);
    }
    CP_COMMIT();
    CP_WAIT0();
    __syncthreads();

    float gacc[2][4];
    float Gacc[8][4];
#pragma unroll
    for (int j = 0; j < 2; j++)
#pragma unroll
        for (int q = 0; q < 4; q++) gacc[j][q] = 0.f;
#pragma unroll
    for (int j = 0; j < 8; j++)
#pragma unroll
        for (int q = 0; q < 4; q++) Gacc[j][q] = 0.f;

    // lane-constant address components
    u32 uLane = (u32)(((lane & 7) + ((lane >> 4) << 3)) * 48 + ((lane >> 3) & 1) * 16);
    u32 bLaneRow = (u32)(((lane & 7) + (((lane >> 3) & 1) << 3)) * 128);
    u32 bXor = (u32)((lane & 7) << 4);
    u32 cOff = (u32)((lane >> 4) * 16);

#pragma unroll
    for (int k = 0; k < 4; k++) {
        u32 kb = (u32)(w * 64 + k * 16);
        u32 Ar[4];
        ldm4t(Ar, sb + kb * 48 + uLane);
        // Gram: B0 = {Ar0, Ar2} (n0-7), B1 = {Ar1, Ar3} (n8-15)
        u32 bg0[2] = {Ar[0], Ar[2]};
        u32 bg1[2] = {Ar[1], Ar[3]};
        mma16816(gacc[0], Ar, bg0);
        mma16816(gacc[1], Ar, bg1);
        u32 brow = sb + 24576 + kb * 128 + bLaneRow;
#pragma unroll
        for (int ng = 0; ng < 4; ng++) {
            u32 Br[4];
            ldm4t(Br, brow + (((u32)(ng * 32) + cOff) ^ bXor));
            mma16816(Gacc[2 * ng], Ar, Br);
            mma16816(Gacc[2 * ng + 1], Ar, Br + 2);
        }
    }

    // r: scalar abs-sum from staged U (before overwrite)
    float rl = 0.f;
    {
        int s = tid & 15, pb2 = (tid >> 4) * 32;
        for (int p2 = 0; p2 < 32; p2++) {
            __half u = *(const __half*)(rsm + (pb2 + p2) * 48 + s * 2);
            rl += fabsf(__half2float(u));
        }
    }
    __syncthreads();

    float* sp = (float*)rsm;
    int g = lane >> 2, t4 = lane & 3;
    int base = w * 1280;
    // Gram partial
#pragma unroll
    for (int h = 0; h < 2; h++) {
        int n = h * 8 + 2 * t4;
        sp[base + g * 16 + n] = gacc[h][0];
        sp[base + g * 16 + n + 1] = gacc[h][1];
        sp[base + (g + 8) * 16 + n] = gacc[h][2];
        sp[base + (g + 8) * 16 + n + 1] = gacc[h][3];
    }
    // G partial
#pragma unroll
    for (int set = 0; set < 8; set++) {
        int c = (set >> 1) * 16 + (set & 1) * 8 + 2 * t4;
        sp[base + 256 + g * 64 + c] = Gacc[set][0];
        sp[base + 256 + g * 64 + c + 1] = Gacc[set][1];
        sp[base + 256 + (g + 8) * 64 + c] = Gacc[set][2];
        sp[base + 256 + (g + 8) * 64 + c + 1] = Gacc[set][3];
    }
    sp[10240 + (tid & 15) * 16 + (tid >> 4)] = rl;
    __syncthreads();

    float* o = g_part + (size_t)(b * NCHUNK + ch) * PART_STRIDE;
    for (int i = tid; i < 1280; i += 256) {
        float a = 0.f;
#pragma unroll
        for (int w2 = 0; w2 < 8; w2++) a += sp[w2 * 1280 + i];
        o[i] = a;
    }
    if (tid < 16) {
        float a = 0.f;
#pragma unroll
        for (int j = 0; j < 16; j++) a += sp[10240 + tid * 16 + j];
        o[1280 + tid] = a;
    }
}

// ================= solve (unchanged) =================
__global__ __launch_bounds__(256)
void solve_kernel() {
    __shared__ float sGram[256];
    __shared__ float sG[1024];
    __shared__ float srr[16];
    __shared__ double A[16][17];
    __shared__ double M[16][17];
    __shared__ double spiv;
    int b = blockIdx.x;
    int tid = threadIdx.x;
    const float* base = g_part + (size_t)b * NCHUNK * PART_STRIDE;
    {
        float a = 0.f;
        for (int ch = 0; ch < NCHUNK; ch++) a += base[ch * PART_STRIDE + tid];
        sGram[tid] = a;
    }
#pragma unroll
    for (int j = 0; j < 4; j++) {
        int e = tid + j * 256;
        float a = 0.f;
        for (int ch = 0; ch < NCHUNK; ch++) a += base[ch * PART_STRIDE + 256 + e];
        sG[e] = a;
    }
    if (tid < 16) {
        float a = 0.f;
        for (int ch = 0; ch < NCHUNK; ch++) a += base[ch * PART_STRIDE + 1280 + tid];
        srr[tid] = 1e-6f + a;
    }
    __syncthreads();
    {
        int i = tid >> 4, t = tid & 15;
        A[i][t] = (double)sGram[tid] / ((double)srr[i] * (double)srr[t]);
        M[i][t] = (i == t) ? 1.0 : 0.0;
    }
    __syncthreads();
    for (int k = 0; k < 16; k++) {
        if (tid == 0) spiv = 1.0 / A[k][k];
        __syncthreads();
        if (tid < 16) { A[k][tid] *= spiv; M[k][tid] *= spiv; }
        __syncthreads();
        int i = tid >> 4, t = tid & 15;
        double f = A[i][k];
        __syncthreads();
        if (i != k) { A[i][t] -= f * A[k][t]; M[i][t] -= f * M[k][t]; }
        __syncthreads();
    }
#pragma unroll
    for (int j = 0; j < 4; j++) {
        int e = tid + j * 256;
        int s = e >> 6, c = e & 63;
        double v = 0.0;
#pragma unroll
        for (int t = 0; t < 16; t++)
            v += M[s][t] * ((double)sG[t * 64 + c] / (double)srr[t]);
        g_PF2[b * 1024 + e] = (float)(v / (double)srr[s]);
    }
}

// ================= fold PF2 into conv2 proj-weights (fp16, ochalf-major) =================
__global__ __launch_bounds__(256)
void w2eff_kernel(const float* __restrict__ Wc) {
    __shared__ float sPF[1024];
    int b = blockIdx.x, tid = threadIdx.x;
    for (int i = tid; i < 1024; i += 256) sPF[i] = g_PF2[b * 1024 + i];
    __syncthreads();
    for (int e = tid; e < 9216; e += 256) {
        int tap = e / 1024, r = e & 1023, o = r >> 4, s = r & 15;
        float v = 0.f;
#pragma unroll
        for (int c = 0; c < 64; c++)
            v += Wc[o * 1152 + (64 + c) * 9 + tap] * sPF[s * 64 + c];
        int oh = o >> 5, ocl = o & 31;
        g_W2[(size_t)b * 9216 + (size_t)(oh * 4608 + tap * 512 + ocl * 16 + s)] =
            __float2half(v);
    }
}

// ================= conv2 =================
#define C2_WU 36864
#define C2_SLOT0 46080
#define C2_SLOTSZ 10560

__device__ __forceinline__ void c2_stage(u32 sb, int b, int x0, int ys, u32 slot, int tid) {
    bool yok = (unsigned)ys < 256u;
    int ysc = yok ? ys : 0;
    for (int i = tid; i < 660; i += 256) {
        if (i < 528) {
            int px = i >> 3, c8 = i & 7;
            int gx = x0 - 1 + px;
            bool ok = yok && (unsigned)gx < 256u;
            int gxc = ((unsigned)gx < 256u) ? gx : 0;
            const void* src = &g_in[PLANE(0, b) +
                                    (((size_t)(ysc * 256 + gxc)) << 6) + c8 * 8];
            u32 dst = sb + slot + (u32)(px * 128) +
                      (u32)((c8 * 16) ^ ((px & 7) << 4));
            cpa16(dst, src, ok);
        } else {
            int j = i - 528;
            int px = j >> 1, hf = j & 1;
            int gx = x0 - 1 + px;
            bool ok = yok && (unsigned)gx < 256u;
            int gxc = ((unsigned)gx < 256u) ? gx : 0;
            const void* src = &g_Uh[((size_t)b * HWN + (size_t)(ysc * 256 + gxc)) * 16 +
                                    hf * 8];
            u32 dst = sb + slot + 8448 + (u32)(px * 32 + hf * 16);
            cpa16(dst, src, ok);
        }
    }
}

__global__ __launch_bounds__(256)
void conv2_kernel(const float* __restrict__ x, float* __restrict__ out) {
    extern __shared__ __align__(16) unsigned char sm[];
    u32 sb = smem_u32(sm);
    int tid = threadIdx.x, lane = tid & 31, wid = tid >> 5;
    int xs = blockIdx.x & 3, oh = blockIdx.x >> 2;
    int b = blockIdx.z, y0 = blockIdx.y * 32, x0 = xs * 64;

    for (int i = tid; i < 36864 / 16; i += 256)
        ((uint4*)sm)[i] = ((const uint4*)(g_Wc2 + oh * 36864))[i];
    for (int i = tid; i < 9216 / 16; i += 256)
        ((uint4*)(sm + C2_WU))[i] =
            ((const uint4*)((const unsigned char*)g_W2 + (size_t)b * 18432 + oh * 9216))[i];

    int i8 = lane & 7, a_mh = (lane >> 3) & 1, a_kh = lane >> 4;
    int b_kh = (lane >> 3) & 1, b_nh = lane >> 4;
    int wm = wid & 1, ym = wid >> 1;
    int apx = wm * 32 + a_mh * 8 + i8;
    u32 ocw[2];
    ocw[0] = (u32)(b_nh * 8 + i8);
    ocw[1] = ocw[0] + 16;
    int g = lane >> 2, t4 = lane & 3;

    for (int r = -1; r <= 4; r++)
        c2_stage(sb, b, x0, y0 + r, C2_SLOT0 + (u32)((r + 6) % 6) * C2_SLOTSZ, tid);
    CP_COMMIT();
    CP_WAIT0();
    __syncthreads();

    for (int t = 0; t < 8; t++) {
        int y = 4 * t + ym;
        int yy = y0 + y;

        float acc[2][4][4];
#pragma unroll
        for (int m = 0; m < 2; m++)
#pragma unroll
            for (int j = 0; j < 4; j++)
#pragma unroll
                for (int q = 0; q < 4; q++) acc[m][j][q] = 0.f;

#pragma unroll
        for (int ky = 0; ky < 3; ky++) {
            u32 sl = sb + C2_SLOT0 + (u32)(((y + ky - 1 + 6) % 6)) * C2_SLOTSZ;
#pragma unroll
            for (int kx = 0; kx < 3; kx++) {
                int tap = ky * 3 + kx;
                int p = apx + kx;
                u32 aoff = (u32)(p * 128);
                u32 asw = (u32)((p & 7) << 4);
#pragma unroll
                for (int kc = 0; kc < 4; kc++) {
                    u32 kb = ((u32)(kc * 32 + a_kh * 16)) ^ asw;
                    u32 Ah0[4], Ah1[4];
                    ldm4(Ah0, sl + aoff + kb);
                    ldm4(Ah1, sl + aoff + 2048 + kb);
                    u32 BH0[4], BH1[4];
                    u32 bcol = (u32)(kc * 32 + b_kh * 16);
                    u32 b0 = sb + (u32)(tap * 4096) + ocw[0] * 128 +
                             (bcol ^ ((ocw[0] & 7) << 4));
                    u32 b1 = sb + (u32)(tap * 4096) + ocw[1] * 128 +
                             (bcol ^ ((ocw[1] & 7) << 4));
                    ldm4(BH0, b0);
                    ldm4(BH1, b1);
#pragma unroll
                    for (int j = 0; j < 2; j++) {
                        mma16816(acc[0][j],     Ah0, BH0 + 2 * j);
                        mma16816(acc[0][2 + j], Ah0, BH1 + 2 * j);
                        mma16816(acc[1][j],     Ah1, BH0 + 2 * j);
                        mma16816(acc[1][2 + j], Ah1, BH1 + 2 * j);
                    }
                }
                {
                    u32 uoff = sl + 8448 + (u32)(p * 32 + a_kh * 16);
                    u32 Ah0[4], Ah1[4];
                    ldm4(Ah0, uoff);
                    ldm4(Ah1, uoff + 512);
                    u32 BH0[4], BH1[4];
                    u32 b0 = sb + C2_WU + (u32)(tap * 1024) + ocw[0] * 32 +
                             (u32)(b_kh * 16);
                    u32 b1 = sb + C2_WU + (u32)(tap * 1024) + ocw[1] * 32 +
                             (u32)(b_kh * 16);
                    ldm4(BH0, b0);
                    ldm4(BH1, b1);
#pragma unroll
                    for (int j = 0; j < 2; j++) {
                        mma16816(acc[0][j],     Ah0, BH0 + 2 * j);
                        mma16816(acc[0][2 + j], Ah0, BH1 + 2 * j);
                        mma16816(acc[1][j],     Ah1, BH0 + 2 * j);
                        mma16816(acc[1][2 + j], Ah1, BH1 + 2 * j);
                    }
                }
            }
        }
        size_t rowb0 = (size_t)yy * 256;
#pragma unroll
        for (int m = 0; m < 2; m++) {
            int px = x0 + wm * 32 + m * 16 + g;
            size_t rowb = rowb0 + px;
#pragma unroll
            for (int j4 = 0; j4 < 4; j4++) {
                int oc = oh * 32 + (j4 >> 1) * 16 + (j4 & 1) * 8 + 2 * t4;
                size_t o0 = ((size_t)(b * 64 + oc) << 16) + rowb;
                size_t o1 = o0 + HWN;
                out[o0] = acc[m][j4][0] + x[o0];
                out[o1] = acc[m][j4][1] + x[o1];
                out[o0 + 8] = acc[m][j4][2] + x[o0 + 8];
                out[o1 + 8] = acc[m][j4][3] + x[o1 + 8];
            }
        }

        __syncthreads();
        if (t < 7) {
#pragma unroll
            for (int r = 5; r <= 8; r++)
                c2_stage(sb, b, x0, y0 + 4 * t + r,
                         C2_SLOT0 + (u32)((4 * t + r) % 6) * C2_SLOTSZ, tid);
            CP_COMMIT();
            CP_WAIT0();
            __syncthreads();
        }
    }
}

// ================= launch =================
extern "C" void kernel_launch(void* const* d_in, const int* in_sizes, int n_in,
                              void* d_out, int out_size) {
    const float* x      = (const float*)d_in[0];
    const float* bridge = (const float*)d_in[1];
    const float* Wsub   = (const float*)d_in[2];
    const float* Wcb    = (const float*)d_in[3];
    float* out = (float*)d_out;

    cudaFuncSetAttribute(conv1_kernel, cudaFuncAttributeMaxDynamicSharedMemorySize, 104448);
    cudaFuncSetAttribute(conv2_kernel, cudaFuncAttributeMaxDynamicSharedMemorySize, 109440);
    cudaFuncSetAttribute(reduce_kernel, cudaFuncAttributeMaxDynamicSharedMemorySize, RED_SM);

    prep_w_kernel<<<288, 256>>>(Wsub, Wcb);
    convert_kernel<<<dim3(1024, 2, 8), 256>>>(x, bridge);
    conv1_kernel<<<dim3(4, 16, 8), 128, 104448>>>();
    reduce_kernel<<<dim3(NCHUNK, BB), 256, RED_SM>>>();
    solve_kernel<<<BB, 256>>>();
    w2eff_kernel<<<BB, 256>>>(Wcb);
    conv2_kernel<<<dim3(8, 8, 8), 256, 109440>>>(x, out);
}